// round 5
// baseline (speedup 1.0000x reference)
#include <cuda_runtime.h>
#include <cuda_bf16.h>
#include <cstdint>

#define BB 128
#define TT 256
#define HH 1024
#define VV 4096

// ---------------- scratch (device globals; no runtime allocation) ----------------
__device__ __align__(16) float g_h0[2][BB*HH];          // ping-pong h0
__device__ __align__(16) float g_p[2][BB*HH];           // ping-pong p = h0@Wih1^T + b
__device__ __align__(16) float g_zero[BB*HH];           // zeros (h0[-1])
__device__ __align__(16) float g_h1[(TT+1)*(BB*HH)];    // slot(i) = g_h1 + (i+1)*BB*HH; slot(-1)=zeros

__global__ void zero_kernel() {
    int i = blockIdx.x * blockDim.x + threadIdx.x;
    if (i < BB*HH) { g_zero[i] = 0.f; g_h1[i] = 0.f; }
}

// ---------------- f32x2 helpers ----------------
__device__ __forceinline__ unsigned long long dup2(float v) {
    unsigned long long r;
    asm("mov.b64 %0, {%1, %1};" : "=l"(r) : "f"(v));
    return r;
}
__device__ __forceinline__ void ffma2(unsigned long long &acc, unsigned long long a, unsigned long long b) {
    asm("fma.rn.f32x2 %0, %1, %2, %0;" : "+l"(acc) : "l"(a), "l"(b));
}
__device__ __forceinline__ float lo32(unsigned long long v){ return __uint_as_float((unsigned)(v & 0xffffffffull)); }
__device__ __forceinline__ float hi32(unsigned long long v){ return __uint_as_float((unsigned)(v >> 32)); }

// ---------------- recurrent step: 3 independent fp32 GEMMs, pipelined across t ----------------
// gemm0: h0[t]   = tanh(x_t*Wih0 + bih0 + bhh0 + h0[t-1]@Whh0^T)      (t in [0,255])
// gemm1: p[t-1]  = h0[t-1]@Wih1^T + bih1 + bhh1                       (t in [1,256])
// gemm2: h1[t-2] = tanh(p[t-2] + h1[t-3]@Whh1^T)                      (t in [2,257])
// Tile: 64(M) x 16(N), K=1024, 128 threads. grid = 3*128 = 384 CTAs.
__global__ void __launch_bounds__(128) step_kernel(
    int t, const float* __restrict__ x,
    const float* __restrict__ Wih0, const float* __restrict__ Whh0,
    const float* __restrict__ bih0, const float* __restrict__ bhh0,
    const float* __restrict__ Wih1, const float* __restrict__ Whh1,
    const float* __restrict__ bih1, const float* __restrict__ bhh1)
{
    // A staged transposed + value-duplicated as f32x2; pad 66 keeps reads conflict-free.
    __shared__ __align__(16) unsigned long long As[2][32][66];  // [buf][k][m<64]
    __shared__ float Bs[2][32][16];                             // [buf][k][n<16]

    int gemm = blockIdx.x >> 7;
    int r = blockIdx.x & 127;
    int m0 = (r & 1) * 64;
    int n0 = (r >> 1) * 16;

    const float *A, *W;
    float *outp;
    if (gemm == 0) {
        if (t >= TT) return;
        A = (t == 0) ? g_zero : g_h0[(t-1)&1];
        W = Whh0; outp = g_h0[t&1];
    } else if (gemm == 1) {
        if (t < 1 || t > TT) return;
        A = g_h0[(t-1)&1]; W = Wih1; outp = g_p[(t-1)&1];
    } else {
        if (t < 2) return;
        A = g_h1 + (size_t)(t-2)*(BB*HH);     // slot(t-3)
        W = Whh1;
        outp = g_h1 + (size_t)(t-1)*(BB*HH);  // slot(t-2)
    }

    int tid = threadIdx.x;
    int pc = tid & 7;          // 8 pair-columns (16 cols)
    int rg = tid >> 3;         // 16 groups of 4 consecutive rows
    int lm = tid >> 3;         // staging lane row 0..15
    int kq = tid & 7;          // staging k-quad 0..7

    unsigned long long acc0=0, acc1=0, acc2=0, acc3=0;

    float4 ra[4]; float4 rb;
    // prefetch tile 0
    #pragma unroll
    for (int i=0;i<4;i++)
        ra[i] = *(const float4*)&A[(size_t)(m0 + lm + i*16)*HH + kq*4];
    rb = *(const float4*)&W[(size_t)(n0 + lm)*HH + kq*4];

    #pragma unroll
    for (int i=0;i<4;i++){
        As[0][kq*4+0][lm+i*16] = dup2(ra[i].x);
        As[0][kq*4+1][lm+i*16] = dup2(ra[i].y);
        As[0][kq*4+2][lm+i*16] = dup2(ra[i].z);
        As[0][kq*4+3][lm+i*16] = dup2(ra[i].w);
    }
    Bs[0][kq*4+0][lm] = rb.x;
    Bs[0][kq*4+1][lm] = rb.y;
    Bs[0][kq*4+2][lm] = rb.z;
    Bs[0][kq*4+3][lm] = rb.w;
    __syncthreads();

    for (int kt = 0; kt < 32; kt++) {
        int buf = kt & 1;
        if (kt < 31) {
            int kb = (kt+1)*32;
            #pragma unroll
            for (int i=0;i<4;i++)
                ra[i] = *(const float4*)&A[(size_t)(m0 + lm + i*16)*HH + kb + kq*4];
            rb = *(const float4*)&W[(size_t)(n0 + lm)*HH + kb + kq*4];
        }
        #pragma unroll
        for (int k=0;k<32;k++){
            unsigned long long b = *(const unsigned long long*)&Bs[buf][k][2*pc];
            const ulonglong2* ap = (const ulonglong2*)&As[buf][k][4*rg];
            ulonglong2 q0 = ap[0];
            ulonglong2 q1 = ap[1];
            ffma2(acc0, q0.x, b);
            ffma2(acc1, q0.y, b);
            ffma2(acc2, q1.x, b);
            ffma2(acc3, q1.y, b);
        }
        if (kt < 31) {
            int nb2 = buf ^ 1;
            #pragma unroll
            for (int i=0;i<4;i++){
                As[nb2][kq*4+0][lm+i*16] = dup2(ra[i].x);
                As[nb2][kq*4+1][lm+i*16] = dup2(ra[i].y);
                As[nb2][kq*4+2][lm+i*16] = dup2(ra[i].z);
                As[nb2][kq*4+3][lm+i*16] = dup2(ra[i].w);
            }
            Bs[nb2][kq*4+0][lm] = rb.x;
            Bs[nb2][kq*4+1][lm] = rb.y;
            Bs[nb2][kq*4+2][lm] = rb.z;
            Bs[nb2][kq*4+3][lm] = rb.w;
        }
        __syncthreads();
    }

    // epilogue
    int n_lo = n0 + 2*pc;
    int m_base = m0 + 4*rg;
    unsigned long long accv[4] = {acc0, acc1, acc2, acc3};

    if (gemm == 0) {
        float blo = bih0[n_lo]   + bhh0[n_lo];
        float bhi = bih0[n_lo+1] + bhh0[n_lo+1];
        float wlo = Wih0[n_lo], whi = Wih0[n_lo+1];
        #pragma unroll
        for (int i=0;i<4;i++){
            int m = m_base + i;
            float xv = x[(size_t)m*TT + t];
            float2 o;
            o.x = tanhf(lo32(accv[i]) + blo + xv*wlo);
            o.y = tanhf(hi32(accv[i]) + bhi + xv*whi);
            *(float2*)&outp[(size_t)m*HH + n_lo] = o;
        }
    } else if (gemm == 1) {
        float blo = bih1[n_lo]   + bhh1[n_lo];
        float bhi = bih1[n_lo+1] + bhh1[n_lo+1];
        #pragma unroll
        for (int i=0;i<4;i++){
            int m = m_base + i;
            float2 o;
            o.x = lo32(accv[i]) + blo;
            o.y = hi32(accv[i]) + bhi;
            *(float2*)&outp[(size_t)m*HH + n_lo] = o;
        }
    } else {
        const float* p = g_p[(t-2)&1];
        #pragma unroll
        for (int i=0;i<4;i++){
            int m = m_base + i;
            float2 pv = *(const float2*)&p[(size_t)m*HH + n_lo];
            float2 o;
            o.x = tanhf(lo32(accv[i]) + pv.x);
            o.y = tanhf(hi32(accv[i]) + pv.y);
            *(float2*)&outp[(size_t)m*HH + n_lo] = o;
        }
    }
}

// ---------------- FC: out[b,t,v] = h1[t,b,:] @ Wfc[v,:] + bfc[v]  (tf32 mma) ----------------
__device__ __forceinline__ float tf32r(float v){
    unsigned u; asm("cvt.rna.tf32.f32 %0, %1;" : "=r"(u) : "f"(v));
    return __uint_as_float(u);
}

__global__ void __launch_bounds__(256) fc_kernel(
    const float* __restrict__ Wfc, const float* __restrict__ bfc, float* __restrict__ out)
{
    __shared__ __align__(16) float As[128][36];   // [m][k] pad 36 -> conflict-free frag reads
    __shared__ float Bs[32][136];                 // [k][n]  pad 136 -> conflict-free frag reads

    const float* Ag = g_h1 + (size_t)BB*HH;       // slots 0..255 => [32768][1024], row m = t*128+b
    int mb = blockIdx.y * 128;
    int nbase = blockIdx.x * 128;
    int tid = threadIdx.x;
    int warp = tid >> 5, lane = tid & 31;
    int wm = warp >> 2, wn = warp & 3;            // 2 x 4 warp grid, warp tile 64x32
    int g = lane >> 2, tig = lane & 3;

    float c[4][4][4];
    #pragma unroll
    for (int i=0;i<4;i++)
        #pragma unroll
        for (int j=0;j<4;j++)
            { c[i][j][0]=0.f; c[i][j][1]=0.f; c[i][j][2]=0.f; c[i][j][3]=0.f; }

    int sm = tid >> 3;   // 0..31 (+p*32)
    int skq = tid & 7;

    float4 rA[4], rB[4];

    // prefetch tile 0
    #pragma unroll
    for (int p=0;p<4;p++){
        rA[p] = *(const float4*)&Ag[(size_t)(mb + sm + p*32)*HH + skq*4];
        rB[p] = *(const float4*)&Wfc[(size_t)(nbase + sm + p*32)*HH + skq*4];
    }
    #pragma unroll
    for (int p=0;p<4;p++){
        float4 a = rA[p];
        *(float4*)&As[sm + p*32][skq*4] =
            make_float4(tf32r(a.x), tf32r(a.y), tf32r(a.z), tf32r(a.w));
        float4 b = rB[p];
        Bs[skq*4+0][sm + p*32] = tf32r(b.x);
        Bs[skq*4+1][sm + p*32] = tf32r(b.y);
        Bs[skq*4+2][sm + p*32] = tf32r(b.z);
        Bs[skq*4+3][sm + p*32] = tf32r(b.w);
    }
    __syncthreads();

    for (int kt = 0; kt < 32; kt++) {
        if (kt < 31) {
            int kb = (kt+1)*32;
            #pragma unroll
            for (int p=0;p<4;p++){
                rA[p] = *(const float4*)&Ag[(size_t)(mb + sm + p*32)*HH + kb + skq*4];
                rB[p] = *(const float4*)&Wfc[(size_t)(nbase + sm + p*32)*HH + kb + skq*4];
            }
        }
        // compute 4 k-steps of 8
        #pragma unroll
        for (int kk=0; kk<4; kk++){
            int ks = kk*8;
            unsigned a[4][4], b[4][2];
            #pragma unroll
            for (int mi=0;mi<4;mi++){
                int mr = wm*64 + mi*16;
                a[mi][0] = __float_as_uint(As[mr+g  ][ks+tig  ]);
                a[mi][1] = __float_as_uint(As[mr+g+8][ks+tig  ]);
                a[mi][2] = __float_as_uint(As[mr+g  ][ks+tig+4]);
                a[mi][3] = __float_as_uint(As[mr+g+8][ks+tig+4]);
            }
            #pragma unroll
            for (int ni=0;ni<4;ni++){
                int nc = wn*32 + ni*8;
                b[ni][0] = __float_as_uint(Bs[ks+tig  ][nc+g]);
                b[ni][1] = __float_as_uint(Bs[ks+tig+4][nc+g]);
            }
            #pragma unroll
            for (int mi=0;mi<4;mi++)
                #pragma unroll
                for (int ni=0;ni<4;ni++){
                    asm volatile(
                        "mma.sync.aligned.m16n8k8.row.col.f32.tf32.tf32.f32 "
                        "{%0,%1,%2,%3}, {%4,%5,%6,%7}, {%8,%9}, {%0,%1,%2,%3};"
                        : "+f"(c[mi][ni][0]), "+f"(c[mi][ni][1]),
                          "+f"(c[mi][ni][2]), "+f"(c[mi][ni][3])
                        : "r"(a[mi][0]), "r"(a[mi][1]), "r"(a[mi][2]), "r"(a[mi][3]),
                          "r"(b[ni][0]), "r"(b[ni][1]));
                }
        }
        __syncthreads();
        if (kt < 31) {
            #pragma unroll
            for (int p=0;p<4;p++){
                float4 a = rA[p];
                *(float4*)&As[sm + p*32][skq*4] =
                    make_float4(tf32r(a.x), tf32r(a.y), tf32r(a.z), tf32r(a.w));
                float4 b = rB[p];
                Bs[skq*4+0][sm + p*32] = tf32r(b.x);
                Bs[skq*4+1][sm + p*32] = tf32r(b.y);
                Bs[skq*4+2][sm + p*32] = tf32r(b.z);
                Bs[skq*4+3][sm + p*32] = tf32r(b.w);
            }
            __syncthreads();
        }
    }

    // epilogue: m = t*128 + b  ->  out[b*T*V + t*V + n]
    #pragma unroll
    for (int mi=0;mi<4;mi++){
        #pragma unroll
        for (int ni=0;ni<4;ni++){
            int nc = nbase + wn*32 + ni*8 + tig*2;
            float2 bias = *(const float2*)&bfc[nc];
            int m1 = mb + wm*64 + mi*16 + g;
            int m2 = m1 + 8;
            {
                int bb = m1 & 127, tt = m1 >> 7;
                float2 o = make_float2(c[mi][ni][0] + bias.x, c[mi][ni][1] + bias.y);
                *(float2*)&out[(size_t)bb*TT*VV + (size_t)tt*VV + nc] = o;
            }
            {
                int bb = m2 & 127, tt = m2 >> 7;
                float2 o = make_float2(c[mi][ni][2] + bias.x, c[mi][ni][3] + bias.y);
                *(float2*)&out[(size_t)bb*TT*VV + (size_t)tt*VV + nc] = o;
            }
        }
    }
}

// ---------------- tail: h_n = stack([h0_final, h1_final]) appended after outs ----------------
__global__ void tail_kernel(float* __restrict__ out){
    int i = blockIdx.x * blockDim.x + threadIdx.x;
    if (i >= 2*BB*HH) return;
    size_t base = (size_t)BB*TT*VV;
    float v = (i < BB*HH) ? g_h0[1][i]                                  // h0[255] (255&1 == 1)
                          : g_h1[(size_t)TT*BB*HH + (i - BB*HH)];       // h1 slot(255)
    out[base + i] = v;
}

extern "C" void kernel_launch(void* const* d_in, const int* in_sizes, int n_in,
                              void* d_out, int out_size) {
    const float* x    = (const float*)d_in[0];
    const float* Wih0 = (const float*)d_in[1];
    const float* Whh0 = (const float*)d_in[2];
    const float* bih0 = (const float*)d_in[3];
    const float* bhh0 = (const float*)d_in[4];
    const float* Wih1 = (const float*)d_in[5];
    const float* Whh1 = (const float*)d_in[6];
    const float* bih1 = (const float*)d_in[7];
    const float* bhh1 = (const float*)d_in[8];
    const float* Wfc  = (const float*)d_in[9];
    const float* bfc  = (const float*)d_in[10];
    float* out = (float*)d_out;

    zero_kernel<<<(BB*HH + 255)/256, 256>>>();

    for (int t = 0; t <= TT + 1; t++)
        step_kernel<<<384, 128>>>(t, x, Wih0, Whh0, bih0, bhh0, Wih1, Whh1, bih1, bhh1);

    fc_kernel<<<dim3(32, 256), 256>>>(Wfc, bfc, out);

    long long need = (long long)BB*TT*VV + 2LL*BB*HH;
    if ((long long)out_size >= need)
        tail_kernel<<<(2*BB*HH + 255)/256, 256>>>(out);
}

// round 6
// speedup vs baseline: 1.5882x; 1.5882x over previous
#include <cuda_runtime.h>
#include <cuda_bf16.h>
#include <cstdint>

#define BB 128
#define TT 256
#define HH 1024
#define VV 4096

// ---------------- scratch (device globals; no runtime allocation) ----------------
__device__ __align__(16) float g_h0[2][BB*HH];          // ping-pong h0
__device__ __align__(16) float g_p[2][BB*HH];           // ping-pong p = h0@Wih1^T + b
__device__ __align__(16) float g_zero[BB*HH];           // zeros (h0[-1])
__device__ __align__(16) float g_h1[(TT+1)*(BB*HH)];    // slot(i) = g_h1 + (i+1)*BB*HH; slot(-1)=zeros

__global__ void zero_kernel() {
    int i = blockIdx.x * blockDim.x + threadIdx.x;
    if (i < BB*HH) { g_zero[i] = 0.f; g_h1[i] = 0.f; }
}

// ---------------- f32x2 helpers ----------------
__device__ __forceinline__ unsigned long long dup2(float v) {
    unsigned long long r;
    asm("mov.b64 %0, {%1, %1};" : "=l"(r) : "f"(v));
    return r;
}
__device__ __forceinline__ unsigned long long pack2(float lo, float hi) {
    unsigned long long r;
    asm("mov.b64 %0, {%1, %2};" : "=l"(r) : "f"(lo), "f"(hi));
    return r;
}
__device__ __forceinline__ void ffma2(unsigned long long &acc, unsigned long long a, unsigned long long b) {
    asm("fma.rn.f32x2 %0, %1, %2, %0;" : "+l"(acc) : "l"(a), "l"(b));
}
__device__ __forceinline__ float lo32(unsigned long long v){ return __uint_as_float((unsigned)(v & 0xffffffffull)); }
__device__ __forceinline__ float hi32(unsigned long long v){ return __uint_as_float((unsigned)(v >> 32)); }

// ---------------- recurrent step: 3 independent fp32 GEMMs, pipelined across t ----------------
// gemm0: h0[t]   = tanh(x_t*Wih0 + bih0 + bhh0 + h0[t-1]@Whh0^T)      (t in [0,255])
// gemm1: p[t-1]  = h0[t-1]@Wih1^T + bih1 + bhh1                       (t in [1,256])
// gemm2: h1[t-2] = tanh(p[t-2] + h1[t-3]@Whh1^T)                      (t in [2,257])
//
// Tile 32(M) x 32(N), K=1024, 64 threads, E=16 outputs/thread (4m x 4n).
// grid = 3 * (4 m-parts * 32 n-parts) = 384 CTAs.
// smem transposed [k][row] with pad 33 (stride == 1 mod 32): all LDS.32 reads
// conflict-free w/ broadcast; transposing STS.32 staging conflict-free.
__global__ void __launch_bounds__(64) step_kernel(
    int t, const float* __restrict__ x,
    const float* __restrict__ Wih0, const float* __restrict__ Whh0,
    const float* __restrict__ bih0, const float* __restrict__ bhh0,
    const float* __restrict__ Wih1, const float* __restrict__ Whh1,
    const float* __restrict__ bih1, const float* __restrict__ bhh1)
{
    __shared__ float As[2][32][33];   // [buf][k][m]
    __shared__ float Bs[2][32][33];   // [buf][k][n]

    int gemm = blockIdx.x >> 7;
    int r = blockIdx.x & 127;
    int m0 = (r & 3) * 32;
    int n0 = (r >> 2) * 32;

    const float *A, *W;
    float *outp;
    if (gemm == 0) {
        if (t >= TT) return;
        A = (t == 0) ? g_zero : g_h0[(t-1)&1];
        W = Whh0; outp = g_h0[t&1];
    } else if (gemm == 1) {
        if (t < 1 || t > TT) return;
        A = g_h0[(t-1)&1]; W = Wih1; outp = g_p[(t-1)&1];
    } else {
        if (t < 2) return;
        A = g_h1 + (size_t)(t-2)*(BB*HH);     // slot(t-3)
        W = Whh1;
        outp = g_h1 + (size_t)(t-1)*(BB*HH);  // slot(t-2)
    }

    int tid  = threadIdx.x;
    int mg   = tid & 7;         // 8 m-groups of 4
    int ng   = tid >> 3;        // 8 n-groups of 4
    int lane = tid & 31;
    int wid  = tid >> 5;        // warp 0 stages A, warp 1 stages B

    // staging map: chunk c (16B) -> row = c>>3, kword = (c&7)*4; lane handles
    // chunks lane+32*i -> rows 4*i + (lane>>3), kword (lane&7)*4. Coalesced LDG,
    // conflict-free transposing STS.32 (row-stride 33).
    int srow = lane >> 3;          // 0..3
    int koff = (lane & 7) * 4;     // 0,4,...,28

    const float* SG = (wid == 0) ? A : W;
    int grow0 = (wid == 0) ? m0 : n0;
    float* Ss = (wid == 0) ? &As[0][0][0] : &Bs[0][0][0];

    unsigned long long acc[4][2];
    #pragma unroll
    for (int i=0;i<4;i++){ acc[i][0]=0; acc[i][1]=0; }

    float4 pf[8];
    // prefetch tile 0
    #pragma unroll
    for (int i=0;i<8;i++)
        pf[i] = *(const float4*)&SG[(size_t)(grow0 + 4*i + srow)*HH + koff];
    #pragma unroll
    for (int i=0;i<8;i++){
        int rw = 4*i + srow;
        Ss[(koff+0)*33 + rw] = pf[i].x;
        Ss[(koff+1)*33 + rw] = pf[i].y;
        Ss[(koff+2)*33 + rw] = pf[i].z;
        Ss[(koff+3)*33 + rw] = pf[i].w;
    }
    __syncthreads();

    for (int kt = 0; kt < 32; kt++) {
        int buf = kt & 1;
        if (kt < 31) {
            int kb = (kt+1)*32;
            #pragma unroll
            for (int i=0;i<8;i++)
                pf[i] = *(const float4*)&SG[(size_t)(grow0 + 4*i + srow)*HH + kb + koff];
        }
        #pragma unroll 8
        for (int k=0;k<32;k++){
            float a0 = As[buf][k][4*mg+0];
            float a1 = As[buf][k][4*mg+1];
            float a2 = As[buf][k][4*mg+2];
            float a3 = As[buf][k][4*mg+3];
            float b0 = Bs[buf][k][4*ng+0];
            float b1 = Bs[buf][k][4*ng+1];
            float b2 = Bs[buf][k][4*ng+2];
            float b3 = Bs[buf][k][4*ng+3];
            unsigned long long bp0 = pack2(b0,b1);
            unsigned long long bp1 = pack2(b2,b3);
            unsigned long long ad;
            ad = dup2(a0); ffma2(acc[0][0], ad, bp0); ffma2(acc[0][1], ad, bp1);
            ad = dup2(a1); ffma2(acc[1][0], ad, bp0); ffma2(acc[1][1], ad, bp1);
            ad = dup2(a2); ffma2(acc[2][0], ad, bp0); ffma2(acc[2][1], ad, bp1);
            ad = dup2(a3); ffma2(acc[3][0], ad, bp0); ffma2(acc[3][1], ad, bp1);
        }
        if (kt < 31) {
            float* Sd = Ss + (buf ^ 1) * (32*33);
            #pragma unroll
            for (int i=0;i<8;i++){
                int rw = 4*i + srow;
                Sd[(koff+0)*33 + rw] = pf[i].x;
                Sd[(koff+1)*33 + rw] = pf[i].y;
                Sd[(koff+2)*33 + rw] = pf[i].z;
                Sd[(koff+3)*33 + rw] = pf[i].w;
            }
        }
        __syncthreads();
    }

    // ---------------- epilogue: 4 rows x 4 cols per thread ----------------
    int n = n0 + 4*ng;
    int mb = m0 + 4*mg;

    if (gemm == 0) {
        float4 bi = *(const float4*)&bih0[n];
        float4 bh = *(const float4*)&bhh0[n];
        float4 w4 = *(const float4*)&Wih0[n];
        float4 bsum = make_float4(bi.x+bh.x, bi.y+bh.y, bi.z+bh.z, bi.w+bh.w);
        #pragma unroll
        for (int i=0;i<4;i++){
            int m = mb + i;
            float xv = x[(size_t)m*TT + t];
            float4 o;
            o.x = tanhf(lo32(acc[i][0]) + bsum.x + xv*w4.x);
            o.y = tanhf(hi32(acc[i][0]) + bsum.y + xv*w4.y);
            o.z = tanhf(lo32(acc[i][1]) + bsum.z + xv*w4.z);
            o.w = tanhf(hi32(acc[i][1]) + bsum.w + xv*w4.w);
            *(float4*)&outp[(size_t)m*HH + n] = o;
        }
    } else if (gemm == 1) {
        float4 bi = *(const float4*)&bih1[n];
        float4 bh = *(const float4*)&bhh1[n];
        float4 bsum = make_float4(bi.x+bh.x, bi.y+bh.y, bi.z+bh.z, bi.w+bh.w);
        #pragma unroll
        for (int i=0;i<4;i++){
            int m = mb + i;
            float4 o;
            o.x = lo32(acc[i][0]) + bsum.x;
            o.y = hi32(acc[i][0]) + bsum.y;
            o.z = lo32(acc[i][1]) + bsum.z;
            o.w = hi32(acc[i][1]) + bsum.w;
            *(float4*)&outp[(size_t)m*HH + n] = o;
        }
    } else {
        const float* p = g_p[(t-2)&1];
        #pragma unroll
        for (int i=0;i<4;i++){
            int m = mb + i;
            float4 pv = *(const float4*)&p[(size_t)m*HH + n];
            float4 o;
            o.x = tanhf(lo32(acc[i][0]) + pv.x);
            o.y = tanhf(hi32(acc[i][0]) + pv.y);
            o.z = tanhf(lo32(acc[i][1]) + pv.z);
            o.w = tanhf(hi32(acc[i][1]) + pv.w);
            *(float4*)&outp[(size_t)m*HH + n] = o;
        }
    }
}

// ---------------- FC: out[b,t,v] = h1[t,b,:] @ Wfc[v,:] + bfc[v]  (tf32 mma) ----------------
__device__ __forceinline__ float tf32r(float v){
    unsigned u; asm("cvt.rna.tf32.f32 %0, %1;" : "=r"(u) : "f"(v));
    return __uint_as_float(u);
}

__global__ void __launch_bounds__(256) fc_kernel(
    const float* __restrict__ Wfc, const float* __restrict__ bfc, float* __restrict__ out)
{
    __shared__ __align__(16) float As[128][36];   // [m][k]
    __shared__ float Bs[32][136];                 // [k][n]

    const float* Ag = g_h1 + (size_t)BB*HH;       // [32768][1024], row m = t*128+b
    int mb = blockIdx.y * 128;
    int nbase = blockIdx.x * 128;
    int tid = threadIdx.x;
    int warp = tid >> 5, lane = tid & 31;
    int wm = warp >> 2, wn = warp & 3;            // 2 x 4 warp grid, warp tile 64x32
    int g = lane >> 2, tig = lane & 3;

    float c[4][4][4];
    #pragma unroll
    for (int i=0;i<4;i++)
        #pragma unroll
        for (int j=0;j<4;j++)
            { c[i][j][0]=0.f; c[i][j][1]=0.f; c[i][j][2]=0.f; c[i][j][3]=0.f; }

    int sm = tid >> 3;
    int skq = tid & 7;

    float4 rA[4], rB[4];

    #pragma unroll
    for (int p=0;p<4;p++){
        rA[p] = *(const float4*)&Ag[(size_t)(mb + sm + p*32)*HH + skq*4];
        rB[p] = *(const float4*)&Wfc[(size_t)(nbase + sm + p*32)*HH + skq*4];
    }
    #pragma unroll
    for (int p=0;p<4;p++){
        float4 a = rA[p];
        *(float4*)&As[sm + p*32][skq*4] =
            make_float4(tf32r(a.x), tf32r(a.y), tf32r(a.z), tf32r(a.w));
        float4 b = rB[p];
        Bs[skq*4+0][sm + p*32] = tf32r(b.x);
        Bs[skq*4+1][sm + p*32] = tf32r(b.y);
        Bs[skq*4+2][sm + p*32] = tf32r(b.z);
        Bs[skq*4+3][sm + p*32] = tf32r(b.w);
    }
    __syncthreads();

    for (int kt = 0; kt < 32; kt++) {
        if (kt < 31) {
            int kb = (kt+1)*32;
            #pragma unroll
            for (int p=0;p<4;p++){
                rA[p] = *(const float4*)&Ag[(size_t)(mb + sm + p*32)*HH + kb + skq*4];
                rB[p] = *(const float4*)&Wfc[(size_t)(nbase + sm + p*32)*HH + kb + skq*4];
            }
        }
        #pragma unroll
        for (int kk=0; kk<4; kk++){
            int ks = kk*8;
            unsigned a[4][4], b[4][2];
            #pragma unroll
            for (int mi=0;mi<4;mi++){
                int mr = wm*64 + mi*16;
                a[mi][0] = __float_as_uint(As[mr+g  ][ks+tig  ]);
                a[mi][1] = __float_as_uint(As[mr+g+8][ks+tig  ]);
                a[mi][2] = __float_as_uint(As[mr+g  ][ks+tig+4]);
                a[mi][3] = __float_as_uint(As[mr+g+8][ks+tig+4]);
            }
            #pragma unroll
            for (int ni=0;ni<4;ni++){
                int nc = wn*32 + ni*8;
                b[ni][0] = __float_as_uint(Bs[ks+tig  ][nc+g]);
                b[ni][1] = __float_as_uint(Bs[ks+tig+4][nc+g]);
            }
            #pragma unroll
            for (int mi=0;mi<4;mi++)
                #pragma unroll
                for (int ni=0;ni<4;ni++){
                    asm volatile(
                        "mma.sync.aligned.m16n8k8.row.col.f32.tf32.tf32.f32 "
                        "{%0,%1,%2,%3}, {%4,%5,%6,%7}, {%8,%9}, {%0,%1,%2,%3};"
                        : "+f"(c[mi][ni][0]), "+f"(c[mi][ni][1]),
                          "+f"(c[mi][ni][2]), "+f"(c[mi][ni][3])
                        : "r"(a[mi][0]), "r"(a[mi][1]), "r"(a[mi][2]), "r"(a[mi][3]),
                          "r"(b[ni][0]), "r"(b[ni][1]));
                }
        }
        __syncthreads();
        if (kt < 31) {
            #pragma unroll
            for (int p=0;p<4;p++){
                float4 a = rA[p];
                *(float4*)&As[sm + p*32][skq*4] =
                    make_float4(tf32r(a.x), tf32r(a.y), tf32r(a.z), tf32r(a.w));
                float4 b = rB[p];
                Bs[skq*4+0][sm + p*32] = tf32r(b.x);
                Bs[skq*4+1][sm + p*32] = tf32r(b.y);
                Bs[skq*4+2][sm + p*32] = tf32r(b.z);
                Bs[skq*4+3][sm + p*32] = tf32r(b.w);
            }
            __syncthreads();
        }
    }

    #pragma unroll
    for (int mi=0;mi<4;mi++){
        #pragma unroll
        for (int ni=0;ni<4;ni++){
            int nc = nbase + wn*32 + ni*8 + tig*2;
            float2 bias = *(const float2*)&bfc[nc];
            int m1 = mb + wm*64 + mi*16 + g;
            int m2 = m1 + 8;
            {
                int bb = m1 & 127, tt = m1 >> 7;
                float2 o = make_float2(c[mi][ni][0] + bias.x, c[mi][ni][1] + bias.y);
                *(float2*)&out[(size_t)bb*TT*VV + (size_t)tt*VV + nc] = o;
            }
            {
                int bb = m2 & 127, tt = m2 >> 7;
                float2 o = make_float2(c[mi][ni][2] + bias.x, c[mi][ni][3] + bias.y);
                *(float2*)&out[(size_t)bb*TT*VV + (size_t)tt*VV + nc] = o;
            }
        }
    }
}

// ---------------- tail: h_n = stack([h0_final, h1_final]) ----------------
__global__ void tail_kernel(float* __restrict__ out){
    int i = blockIdx.x * blockDim.x + threadIdx.x;
    if (i >= 2*BB*HH) return;
    size_t base = (size_t)BB*TT*VV;
    float v = (i < BB*HH) ? g_h0[1][i]
                          : g_h1[(size_t)TT*BB*HH + (i - BB*HH)];
    out[base + i] = v;
}

extern "C" void kernel_launch(void* const* d_in, const int* in_sizes, int n_in,
                              void* d_out, int out_size) {
    const float* x    = (const float*)d_in[0];
    const float* Wih0 = (const float*)d_in[1];
    const float* Whh0 = (const float*)d_in[2];
    const float* bih0 = (const float*)d_in[3];
    const float* bhh0 = (const float*)d_in[4];
    const float* Wih1 = (const float*)d_in[5];
    const float* Whh1 = (const float*)d_in[6];
    const float* bih1 = (const float*)d_in[7];
    const float* bhh1 = (const float*)d_in[8];
    const float* Wfc  = (const float*)d_in[9];
    const float* bfc  = (const float*)d_in[10];
    float* out = (float*)d_out;

    zero_kernel<<<(BB*HH + 255)/256, 256>>>();

    for (int t = 0; t <= TT + 1; t++)
        step_kernel<<<384, 64>>>(t, x, Wih0, Whh0, bih0, bhh0, Wih1, Whh1, bih1, bhh1);

    fc_kernel<<<dim3(32, 256), 256>>>(Wfc, bfc, out);

    long long need = (long long)BB*TT*VV + 2LL*BB*HH;
    if ((long long)out_size >= need)
        tail_kernel<<<(2*BB*HH + 255)/256, 256>>>(out);
}

// round 10
// speedup vs baseline: 1.9510x; 1.2284x over previous
#include <cuda_runtime.h>
#include <cuda_bf16.h>
#include <cstdint>

#define BB 128
#define TT 256
#define HH 1024
#define VV 4096

// ---------------- scratch (device globals; no runtime allocation) ----------------
__device__ __align__(16) float g_h0[2][BB*HH];          // ping-pong h0
__device__ __align__(16) float g_p[2][BB*HH];           // ping-pong p = h0@Wih1^T + b
__device__ __align__(16) float g_zero[BB*HH];           // zeros (h0[-1])
__device__ __align__(16) float g_h1[(TT+1)*(BB*HH)];    // slot(i) = g_h1 + (i+1)*BB*HH; slot(-1)=zeros

__global__ void zero_kernel() {
    int i = blockIdx.x * blockDim.x + threadIdx.x;
    if (i < BB*HH) { g_zero[i] = 0.f; g_h1[i] = 0.f; }
}

__device__ __forceinline__ float tf32r(float v){
    unsigned u; asm("cvt.rna.tf32.f32 %0, %1;" : "=r"(u) : "f"(v));
    return __uint_as_float(u);
}

__device__ __forceinline__ void mma_tf32(float* c, const unsigned* a, const unsigned* b){
    asm volatile(
        "mma.sync.aligned.m16n8k8.row.col.f32.tf32.tf32.f32 "
        "{%0,%1,%2,%3}, {%4,%5,%6,%7}, {%8,%9}, {%0,%1,%2,%3};"
        : "+f"(c[0]), "+f"(c[1]), "+f"(c[2]), "+f"(c[3])
        : "r"(a[0]), "r"(a[1]), "r"(a[2]), "r"(a[3]), "r"(b[0]), "r"(b[1]));
}

// ---------------- recurrent step: 3 independent GEMMs on tensor cores (3xTF32) ----------------
// gemm0: h0[t]   = tanh(x_t*Wih0 + bih0 + bhh0 + h0[t-1]@Whh0^T)      (t in [0,255])
// gemm1: p[t-1]  = h0[t-1]@Wih1^T + bih1 + bhh1                       (t in [1,256])
// gemm2: h1[t-2] = tanh(p[t-2] + h1[t-3]@Whh1^T)                      (t in [2,257])
//
// CTA tile 64(M) x 64(N), K=1024, 128 threads, warp tile 32x32 via m16n8k8.
// grid = 3 * (2 m-parts * 16 n-parts) = 96 CTAs.
// All smem tiles in [row][36] layout; B fragments read directly from [n][k]
// (bank = 4g+tig, conflict-free). Staging: coalesced LDG.128 + STS.128.
__global__ void __launch_bounds__(128) step_kernel(
    int t, const float* __restrict__ x,
    const float* __restrict__ Wih0, const float* __restrict__ Whh0,
    const float* __restrict__ bih0, const float* __restrict__ bhh0,
    const float* __restrict__ Wih1, const float* __restrict__ Whh1,
    const float* __restrict__ bih1, const float* __restrict__ bhh1)
{
    __shared__ float Ah[64][36], Al[64][36];
    __shared__ float Bh[64][36], Bl[64][36];

    int gemm = blockIdx.x >> 5;
    int r = blockIdx.x & 31;
    int m0 = (r >> 4) << 6;     // 0 or 64
    int n0 = (r & 15) << 6;     // 0..960

    const float *A, *W;
    float *outp;
    if (gemm == 0) {
        if (t >= TT) return;
        A = (t == 0) ? g_zero : g_h0[(t-1)&1];
        W = Whh0; outp = g_h0[t&1];
    } else if (gemm == 1) {
        if (t < 1 || t > TT) return;
        A = g_h0[(t-1)&1]; W = Wih1; outp = g_p[(t-1)&1];
    } else {
        if (t < 2) return;
        A = g_h1 + (size_t)(t-2)*(BB*HH);     // slot(t-3)
        W = Whh1;
        outp = g_h1 + (size_t)(t-1)*(BB*HH);  // slot(t-2)
    }

    int tid  = threadIdx.x;
    int warp = tid >> 5, lane = tid & 31;
    int wm = warp >> 1, wn = warp & 1;        // 2x2 warp grid, warp tile 32x32
    int g  = lane >> 2, tig = lane & 3;
    int sm  = tid >> 3;    // staging row group 0..15
    int skq = tid & 7;     // staging k-quad 0..7

    float cm[2][4][4], ce[2][4][4];
    #pragma unroll
    for (int i=0;i<2;i++)
        #pragma unroll
        for (int j=0;j<4;j++)
            #pragma unroll
            for (int q=0;q<4;q++){ cm[i][j][q]=0.f; ce[i][j][q]=0.f; }

    float4 rA[4], rB[4];

    // prefetch chunk 0
    #pragma unroll
    for (int p=0;p<4;p++){
        rA[p] = *(const float4*)&A[(size_t)(m0 + sm + 16*p)*HH + skq*4];
        rB[p] = *(const float4*)&W[(size_t)(n0 + sm + 16*p)*HH + skq*4];
    }
    #pragma unroll
    for (int p=0;p<4;p++){
        int row = sm + 16*p;
        float4 v = rA[p];
        float4 h = make_float4(tf32r(v.x), tf32r(v.y), tf32r(v.z), tf32r(v.w));
        float4 l = make_float4(tf32r(v.x-h.x), tf32r(v.y-h.y), tf32r(v.z-h.z), tf32r(v.w-h.w));
        *(float4*)&Ah[row][skq*4] = h;
        *(float4*)&Al[row][skq*4] = l;
        v = rB[p];
        h = make_float4(tf32r(v.x), tf32r(v.y), tf32r(v.z), tf32r(v.w));
        l = make_float4(tf32r(v.x-h.x), tf32r(v.y-h.y), tf32r(v.z-h.z), tf32r(v.w-h.w));
        *(float4*)&Bh[row][skq*4] = h;
        *(float4*)&Bl[row][skq*4] = l;
    }
    __syncthreads();

    for (int kt = 0; kt < 32; kt++) {
        if (kt < 31) {
            int kb = (kt+1)*32;
            #pragma unroll
            for (int p=0;p<4;p++){
                rA[p] = *(const float4*)&A[(size_t)(m0 + sm + 16*p)*HH + kb + skq*4];
                rB[p] = *(const float4*)&W[(size_t)(n0 + sm + 16*p)*HH + kb + skq*4];
            }
        }
        #pragma unroll
        for (int kk=0; kk<4; kk++){
            int ks = kk*8;
            unsigned ah[2][4], al[2][4], bh[4][2], bl[4][2];
            #pragma unroll
            for (int mi=0;mi<2;mi++){
                int mr = wm*32 + mi*16;
                ah[mi][0] = __float_as_uint(Ah[mr+g  ][ks+tig  ]);
                ah[mi][1] = __float_as_uint(Ah[mr+g+8][ks+tig  ]);
                ah[mi][2] = __float_as_uint(Ah[mr+g  ][ks+tig+4]);
                ah[mi][3] = __float_as_uint(Ah[mr+g+8][ks+tig+4]);
                al[mi][0] = __float_as_uint(Al[mr+g  ][ks+tig  ]);
                al[mi][1] = __float_as_uint(Al[mr+g+8][ks+tig  ]);
                al[mi][2] = __float_as_uint(Al[mr+g  ][ks+tig+4]);
                al[mi][3] = __float_as_uint(Al[mr+g+8][ks+tig+4]);
            }
            #pragma unroll
            for (int ni=0;ni<4;ni++){
                int nc = wn*32 + ni*8;
                bh[ni][0] = __float_as_uint(Bh[nc+g][ks+tig  ]);
                bh[ni][1] = __float_as_uint(Bh[nc+g][ks+tig+4]);
                bl[ni][0] = __float_as_uint(Bl[nc+g][ks+tig  ]);
                bl[ni][1] = __float_as_uint(Bl[nc+g][ks+tig+4]);
            }
            #pragma unroll
            for (int mi=0;mi<2;mi++)
                #pragma unroll
                for (int ni=0;ni<4;ni++){
                    mma_tf32(cm[mi][ni], ah[mi], bh[ni]);   // hi*hi -> main acc
                    mma_tf32(ce[mi][ni], al[mi], bh[ni]);   // lo*hi -> err acc
                    mma_tf32(ce[mi][ni], ah[mi], bl[ni]);   // hi*lo -> err acc
                }
        }
        __syncthreads();
        if (kt < 31) {
            #pragma unroll
            for (int p=0;p<4;p++){
                int row = sm + 16*p;
                float4 v = rA[p];
                float4 h = make_float4(tf32r(v.x), tf32r(v.y), tf32r(v.z), tf32r(v.w));
                float4 l = make_float4(tf32r(v.x-h.x), tf32r(v.y-h.y), tf32r(v.z-h.z), tf32r(v.w-h.w));
                *(float4*)&Ah[row][skq*4] = h;
                *(float4*)&Al[row][skq*4] = l;
                v = rB[p];
                h = make_float4(tf32r(v.x), tf32r(v.y), tf32r(v.z), tf32r(v.w));
                l = make_float4(tf32r(v.x-h.x), tf32r(v.y-h.y), tf32r(v.z-h.z), tf32r(v.w-h.w));
                *(float4*)&Bh[row][skq*4] = h;
                *(float4*)&Bl[row][skq*4] = l;
            }
            __syncthreads();
        }
    }

    // ---------------- epilogue ----------------
    #pragma unroll
    for (int mi=0;mi<2;mi++){
        #pragma unroll
        for (int ni=0;ni<4;ni++){
            float v0 = cm[mi][ni][0] + ce[mi][ni][0];
            float v1 = cm[mi][ni][1] + ce[mi][ni][1];
            float v2 = cm[mi][ni][2] + ce[mi][ni][2];
            float v3 = cm[mi][ni][3] + ce[mi][ni][3];
            int n  = n0 + wn*32 + ni*8 + tig*2;
            int m1 = m0 + wm*32 + mi*16 + g;
            int m2 = m1 + 8;

            if (gemm == 0) {
                float2 bi = *(const float2*)&bih0[n];
                float2 bh2 = *(const float2*)&bhh0[n];
                float2 w2 = *(const float2*)&Wih0[n];
                float bsx = bi.x + bh2.x, bsy = bi.y + bh2.y;
                float xv1 = x[(size_t)m1*TT + t];
                float xv2 = x[(size_t)m2*TT + t];
                float2 o1 = make_float2(tanhf(v0 + bsx + xv1*w2.x),
                                        tanhf(v1 + bsy + xv1*w2.y));
                float2 o2 = make_float2(tanhf(v2 + bsx + xv2*w2.x),
                                        tanhf(v3 + bsy + xv2*w2.y));
                *(float2*)&outp[(size_t)m1*HH + n] = o1;
                *(float2*)&outp[(size_t)m2*HH + n] = o2;
            } else if (gemm == 1) {
                float2 bi = *(const float2*)&bih1[n];
                float2 bh2 = *(const float2*)&bhh1[n];
                float bsx = bi.x + bh2.x, bsy = bi.y + bh2.y;
                float2 o1 = make_float2(v0 + bsx, v1 + bsy);
                float2 o2 = make_float2(v2 + bsx, v3 + bsy);
                *(float2*)&outp[(size_t)m1*HH + n] = o1;
                *(float2*)&outp[(size_t)m2*HH + n] = o2;
            } else {
                const float* pbuf = g_p[(t-2)&1];
                float2 p1 = *(const float2*)&pbuf[(size_t)m1*HH + n];
                float2 p2 = *(const float2*)&pbuf[(size_t)m2*HH + n];
                float2 o1 = make_float2(tanhf(v0 + p1.x), tanhf(v1 + p1.y));
                float2 o2 = make_float2(tanhf(v2 + p2.x), tanhf(v3 + p2.y));
                *(float2*)&outp[(size_t)m1*HH + n] = o1;
                *(float2*)&outp[(size_t)m2*HH + n] = o2;
            }
        }
    }
}

// ---------------- FC: out[b,t,v] = h1[t,b,:] @ Wfc[v,:] + bfc[v]  (tf32 mma) ----------------
__global__ void __launch_bounds__(256) fc_kernel(
    const float* __restrict__ Wfc, const float* __restrict__ bfc, float* __restrict__ out)
{
    __shared__ __align__(16) float As[128][36];   // [m][k]
    __shared__ float Bs[32][136];                 // [k][n]

    const float* Ag = g_h1 + (size_t)BB*HH;       // [32768][1024], row m = t*128+b
    int mb = blockIdx.y * 128;
    int nbase = blockIdx.x * 128;
    int tid = threadIdx.x;
    int warp = tid >> 5, lane = tid & 31;
    int wm = warp >> 2, wn = warp & 3;            // 2 x 4 warp grid, warp tile 64x32
    int g = lane >> 2, tig = lane & 3;

    float c[4][4][4];
    #pragma unroll
    for (int i=0;i<4;i++)
        #pragma unroll
        for (int j=0;j<4;j++)
            { c[i][j][0]=0.f; c[i][j][1]=0.f; c[i][j][2]=0.f; c[i][j][3]=0.f; }

    int sm = tid >> 3;
    int skq = tid & 7;

    float4 rA[4], rB[4];

    #pragma unroll
    for (int p=0;p<4;p++){
        rA[p] = *(const float4*)&Ag[(size_t)(mb + sm + p*32)*HH + skq*4];
        rB[p] = *(const float4*)&Wfc[(size_t)(nbase + sm + p*32)*HH + skq*4];
    }
    #pragma unroll
    for (int p=0;p<4;p++){
        float4 a = rA[p];
        *(float4*)&As[sm + p*32][skq*4] =
            make_float4(tf32r(a.x), tf32r(a.y), tf32r(a.z), tf32r(a.w));
        float4 b = rB[p];
        Bs[skq*4+0][sm + p*32] = tf32r(b.x);
        Bs[skq*4+1][sm + p*32] = tf32r(b.y);
        Bs[skq*4+2][sm + p*32] = tf32r(b.z);
        Bs[skq*4+3][sm + p*32] = tf32r(b.w);
    }
    __syncthreads();

    for (int kt = 0; kt < 32; kt++) {
        if (kt < 31) {
            int kb = (kt+1)*32;
            #pragma unroll
            for (int p=0;p<4;p++){
                rA[p] = *(const float4*)&Ag[(size_t)(mb + sm + p*32)*HH + kb + skq*4];
                rB[p] = *(const float4*)&Wfc[(size_t)(nbase + sm + p*32)*HH + kb + skq*4];
            }
        }
        #pragma unroll
        for (int kk=0; kk<4; kk++){
            int ks = kk*8;
            unsigned a[4][4], b[4][2];
            #pragma unroll
            for (int mi=0;mi<4;mi++){
                int mr = wm*64 + mi*16;
                a[mi][0] = __float_as_uint(As[mr+g  ][ks+tig  ]);
                a[mi][1] = __float_as_uint(As[mr+g+8][ks+tig  ]);
                a[mi][2] = __float_as_uint(As[mr+g  ][ks+tig+4]);
                a[mi][3] = __float_as_uint(As[mr+g+8][ks+tig+4]);
            }
            #pragma unroll
            for (int ni=0;ni<4;ni++){
                int nc = wn*32 + ni*8;
                b[ni][0] = __float_as_uint(Bs[ks+tig  ][nc+g]);
                b[ni][1] = __float_as_uint(Bs[ks+tig+4][nc+g]);
            }
            #pragma unroll
            for (int mi=0;mi<4;mi++)
                #pragma unroll
                for (int ni=0;ni<4;ni++){
                    asm volatile(
                        "mma.sync.aligned.m16n8k8.row.col.f32.tf32.tf32.f32 "
                        "{%0,%1,%2,%3}, {%4,%5,%6,%7}, {%8,%9}, {%0,%1,%2,%3};"
                        : "+f"(c[mi][ni][0]), "+f"(c[mi][ni][1]),
                          "+f"(c[mi][ni][2]), "+f"(c[mi][ni][3])
                        : "r"(a[mi][0]), "r"(a[mi][1]), "r"(a[mi][2]), "r"(a[mi][3]),
                          "r"(b[ni][0]), "r"(b[ni][1]));
                }
        }
        __syncthreads();
        if (kt < 31) {
            #pragma unroll
            for (int p=0;p<4;p++){
                float4 a = rA[p];
                *(float4*)&As[sm + p*32][skq*4] =
                    make_float4(tf32r(a.x), tf32r(a.y), tf32r(a.z), tf32r(a.w));
                float4 b = rB[p];
                Bs[skq*4+0][sm + p*32] = tf32r(b.x);
                Bs[skq*4+1][sm + p*32] = tf32r(b.y);
                Bs[skq*4+2][sm + p*32] = tf32r(b.z);
                Bs[skq*4+3][sm + p*32] = tf32r(b.w);
            }
            __syncthreads();
        }
    }

    #pragma unroll
    for (int mi=0;mi<4;mi++){
        #pragma unroll
        for (int ni=0;ni<4;ni++){
            int nc = nbase + wn*32 + ni*8 + tig*2;
            float2 bias = *(const float2*)&bfc[nc];
            int m1 = mb + wm*64 + mi*16 + g;
            int m2 = m1 + 8;
            {
                int bb = m1 & 127, tt = m1 >> 7;
                float2 o = make_float2(c[mi][ni][0] + bias.x, c[mi][ni][1] + bias.y);
                *(float2*)&out[(size_t)bb*TT*VV + (size_t)tt*VV + nc] = o;
            }
            {
                int bb = m2 & 127, tt = m2 >> 7;
                float2 o = make_float2(c[mi][ni][2] + bias.x, c[mi][ni][3] + bias.y);
                *(float2*)&out[(size_t)bb*TT*VV + (size_t)tt*VV + nc] = o;
            }
        }
    }
}

// ---------------- tail: h_n = stack([h0_final, h1_final]) ----------------
__global__ void tail_kernel(float* __restrict__ out){
    int i = blockIdx.x * blockDim.x + threadIdx.x;
    if (i >= 2*BB*HH) return;
    size_t base = (size_t)BB*TT*VV;
    float v = (i < BB*HH) ? g_h0[1][i]
                          : g_h1[(size_t)TT*BB*HH + (i - BB*HH)];
    out[base + i] = v;
}

extern "C" void kernel_launch(void* const* d_in, const int* in_sizes, int n_in,
                              void* d_out, int out_size) {
    const float* x    = (const float*)d_in[0];
    const float* Wih0 = (const float*)d_in[1];
    const float* Whh0 = (const float*)d_in[2];
    const float* bih0 = (const float*)d_in[3];
    const float* bhh0 = (const float*)d_in[4];
    const float* Wih1 = (const float*)d_in[5];
    const float* Whh1 = (const float*)d_in[6];
    const float* bih1 = (const float*)d_in[7];
    const float* bfc_dummy = (const float*)d_in[8];
    (void)bfc_dummy;
    const float* bhh1 = (const float*)d_in[8];
    const float* Wfc  = (const float*)d_in[9];
    const float* bfc  = (const float*)d_in[10];
    float* out = (float*)d_out;

    zero_kernel<<<(BB*HH + 255)/256, 256>>>();

    for (int t = 0; t <= TT + 1; t++)
        step_kernel<<<96, 128>>>(t, x, Wih0, Whh0, bih0, bhh0, Wih1, Whh1, bih1, bhh1);

    fc_kernel<<<dim3(32, 256), 256>>>(Wfc, bfc, out);

    long long need = (long long)BB*TT*VV + 2LL*BB*HH;
    if ((long long)out_size >= need)
        tail_kernel<<<(2*BB*HH + 255)/256, 256>>>(out);
}

// round 13
// speedup vs baseline: 2.0349x; 1.0430x over previous
#include <cuda_runtime.h>
#include <cuda_bf16.h>
#include <cstdint>

#define BB 128
#define TT 256
#define HH 1024
#define VV 4096

// ---------------- scratch (device globals; no runtime allocation) ----------------
__device__ __align__(16) float g_h0[2][BB*HH];          // ping-pong h0
__device__ __align__(16) float g_p[2][BB*HH];           // ping-pong p = h0@Wih1^T + b
__device__ __align__(16) float g_zero[BB*HH];           // zeros (h0[-1])
__device__ __align__(16) float g_h1[(TT+1)*(BB*HH)];    // slot(i) = g_h1 + (i+1)*BB*HH; slot(-1)=zeros

__global__ void zero_kernel() {
    int i = blockIdx.x * blockDim.x + threadIdx.x;
    if (i < BB*HH) { g_zero[i] = 0.f; g_h1[i] = 0.f; }
}

__device__ __forceinline__ float tf32r(float v){
    unsigned u; asm("cvt.rna.tf32.f32 %0, %1;" : "=r"(u) : "f"(v));
    return __uint_as_float(u);
}

__device__ __forceinline__ void mma_tf32(float* c, const unsigned* a, const unsigned* b){
    asm volatile(
        "mma.sync.aligned.m16n8k8.row.col.f32.tf32.tf32.f32 "
        "{%0,%1,%2,%3}, {%4,%5,%6,%7}, {%8,%9}, {%0,%1,%2,%3};"
        : "+f"(c[0]), "+f"(c[1]), "+f"(c[2]), "+f"(c[3])
        : "r"(a[0]), "r"(a[1]), "r"(a[2]), "r"(a[3]), "r"(b[0]), "r"(b[1]));
}

// ---------------- recurrent step: 3 independent GEMMs, occupancy-first ----------------
// gemm0: h0[t]   = tanh(x_t*Wih0 + bih0 + bhh0 + h0[t-1]@Whh0^T)      (t in [0,255])
// gemm1: p[t-1]  = h0[t-1]@Wih1^T + bih1 + bhh1                       (t in [1,256])
// gemm2: h1[t-2] = tanh(p[t-2] + h1[t-3]@Whh1^T)                      (t in [2,257])
//
// CTA tile 32(M) x 32(N), 128 threads = 4 warps. Each warp owns a private
// K=256 slice (16 chunks of k16) with warp-private smem staging -> NO
// __syncthreads in the mainloop (only __syncwarp). 3xTF32 split in-register.
// grid = 3 * (4 m-parts * 32 n-parts) = 384 CTAs -> 3 CTAs/SM, one wave.
__global__ void __launch_bounds__(128, 3) step_kernel(
    int t, const float* __restrict__ x,
    const float* __restrict__ Wih0, const float* __restrict__ Whh0,
    const float* __restrict__ bih0, const float* __restrict__ bhh0,
    const float* __restrict__ Wih1, const float* __restrict__ Whh1,
    const float* __restrict__ bih1, const float* __restrict__ bhh1)
{
    // [warp][role 0=Ah 1=Al 2=Bh 3=Bl][row 32][k16 pad 20] = 40 KB
    // pad 20: frag LDS banks (20g+tig)&31 all distinct -> conflict-free.
    __shared__ __align__(16) float SM[4][4][32][20];

    int gemm = blockIdx.x >> 7;
    int r = blockIdx.x & 127;
    int m0 = (r & 3) << 5;      // 0,32,64,96
    int n0 = (r >> 2) << 5;     // 0..992

    const float *A, *W;
    float *outp;
    if (gemm == 0) {
        if (t >= TT) return;
        A = (t == 0) ? g_zero : g_h0[(t-1)&1];
        W = Whh0; outp = g_h0[t&1];
    } else if (gemm == 1) {
        if (t < 1 || t > TT) return;
        A = g_h0[(t-1)&1]; W = Wih1; outp = g_p[(t-1)&1];
    } else {
        if (t < 2) return;
        A = g_h1 + (size_t)(t-2)*(BB*HH);     // slot(t-3)
        W = Whh1;
        outp = g_h1 + (size_t)(t-1)*(BB*HH);  // slot(t-2)
    }

    int tid  = threadIdx.x;
    int warp = tid >> 5, lane = tid & 31;
    int g  = lane >> 2, tig = lane & 3;
    int srow = lane >> 2;          // staging row base 0..7
    int kcol = (lane & 3) * 4;     // staging k column 0,4,8,12

    float (*Ah)[20] = SM[warp][0];
    float (*Al)[20] = SM[warp][1];
    float (*Bh)[20] = SM[warp][2];
    float (*Bl)[20] = SM[warp][3];

    float cm[2][4][4];
    #pragma unroll
    for (int i=0;i<2;i++)
        #pragma unroll
        for (int j=0;j<4;j++)
            #pragma unroll
            for (int q=0;q<4;q++) cm[i][j][q]=0.f;

    int kbase = warp << 8;   // K slice [warp*256, warp*256+256)

    float4 rA[4], rB[4];
    // prologue: LDG chunk 0
    #pragma unroll
    for (int i=0;i<4;i++){
        rA[i] = *(const float4*)&A[(size_t)(m0 + srow + 8*i)*HH + kbase + kcol];
        rB[i] = *(const float4*)&W[(size_t)(n0 + srow + 8*i)*HH + kbase + kcol];
    }

    for (int kt = 0; kt < 16; kt++) {
        // split + stage chunk kt (warp-private smem)
        #pragma unroll
        for (int i=0;i<4;i++){
            int row = srow + 8*i;
            float4 v = rA[i];
            float4 h = make_float4(tf32r(v.x), tf32r(v.y), tf32r(v.z), tf32r(v.w));
            float4 l = make_float4(tf32r(v.x-h.x), tf32r(v.y-h.y), tf32r(v.z-h.z), tf32r(v.w-h.w));
            *(float4*)&Ah[row][kcol] = h;
            *(float4*)&Al[row][kcol] = l;
            v = rB[i];
            h = make_float4(tf32r(v.x), tf32r(v.y), tf32r(v.z), tf32r(v.w));
            l = make_float4(tf32r(v.x-h.x), tf32r(v.y-h.y), tf32r(v.z-h.z), tf32r(v.w-h.w));
            *(float4*)&Bh[row][kcol] = h;
            *(float4*)&Bl[row][kcol] = l;
        }
        // prefetch chunk kt+1 (latency hidden behind compute below)
        if (kt < 15) {
            int kb = kbase + (kt+1)*16;
            #pragma unroll
            for (int i=0;i<4;i++){
                rA[i] = *(const float4*)&A[(size_t)(m0 + srow + 8*i)*HH + kb + kcol];
                rB[i] = *(const float4*)&W[(size_t)(n0 + srow + 8*i)*HH + kb + kcol];
            }
        }
        __syncwarp();
        // compute chunk kt: 2 k8 slices
        #pragma unroll
        for (int kk=0; kk<2; kk++){
            int ks = kk*8;
            unsigned ah[2][4], al[2][4], bh[4][2], bl[4][2];
            #pragma unroll
            for (int mi=0;mi<2;mi++){
                int mr = mi*16;
                ah[mi][0] = __float_as_uint(Ah[mr+g  ][ks+tig  ]);
                ah[mi][1] = __float_as_uint(Ah[mr+g+8][ks+tig  ]);
                ah[mi][2] = __float_as_uint(Ah[mr+g  ][ks+tig+4]);
                ah[mi][3] = __float_as_uint(Ah[mr+g+8][ks+tig+4]);
                al[mi][0] = __float_as_uint(Al[mr+g  ][ks+tig  ]);
                al[mi][1] = __float_as_uint(Al[mr+g+8][ks+tig  ]);
                al[mi][2] = __float_as_uint(Al[mr+g  ][ks+tig+4]);
                al[mi][3] = __float_as_uint(Al[mr+g+8][ks+tig+4]);
            }
            #pragma unroll
            for (int ni=0;ni<4;ni++){
                int nc = ni*8;
                bh[ni][0] = __float_as_uint(Bh[nc+g][ks+tig  ]);
                bh[ni][1] = __float_as_uint(Bh[nc+g][ks+tig+4]);
                bl[ni][0] = __float_as_uint(Bl[nc+g][ks+tig  ]);
                bl[ni][1] = __float_as_uint(Bl[nc+g][ks+tig+4]);
            }
            #pragma unroll
            for (int mi=0;mi<2;mi++)
                #pragma unroll
                for (int ni=0;ni<4;ni++){
                    mma_tf32(cm[mi][ni], ah[mi], bh[ni]);
                    mma_tf32(cm[mi][ni], al[mi], bh[ni]);
                    mma_tf32(cm[mi][ni], ah[mi], bl[ni]);
                }
        }
        __syncwarp();   // protect staging WAR for next iteration
    }

    // ---------------- cross-warp K reduction ----------------
    // reuse this warp's staging region (2560 floats) as a [32][36] partial tile
    // C-fragment layout: {c0,c1} -> (row g,   cols nc,nc+1)
    //                    {c2,c3} -> (row g+8, cols nc,nc+1)
    float* red = &SM[warp][0][0][0];
    #pragma unroll
    for (int mi=0;mi<2;mi++){
        #pragma unroll
        for (int ni=0;ni<4;ni++){
            int nc = ni*8 + tig*2;
            int r1 = mi*16 + g, r2 = r1 + 8;
            *(float2*)&red[r1*36 + nc] = make_float2(cm[mi][ni][0], cm[mi][ni][1]);
            *(float2*)&red[r2*36 + nc] = make_float2(cm[mi][ni][2], cm[mi][ni][3]);
        }
    }
    __syncthreads();

    // each thread owns one row (rr) and 8 cols (cb..cb+7)
    int rr = tid >> 2, cb = (tid & 3) * 8;
    float4 v0 = make_float4(0,0,0,0), v1 = make_float4(0,0,0,0);
    #pragma unroll
    for (int w=0; w<4; w++){
        const float* rw = &SM[w][0][0][0];
        float4 a = *(const float4*)&rw[rr*36 + cb];
        float4 b = *(const float4*)&rw[rr*36 + cb + 4];
        v0.x += a.x; v0.y += a.y; v0.z += a.z; v0.w += a.w;
        v1.x += b.x; v1.y += b.y; v1.z += b.z; v1.w += b.w;
    }

    int m = m0 + rr, n = n0 + cb;

    if (gemm == 0) {
        float4 bi0 = *(const float4*)&bih0[n];
        float4 bh0 = *(const float4*)&bhh0[n];
        float4 w0  = *(const float4*)&Wih0[n];
        float4 bi1 = *(const float4*)&bih0[n+4];
        float4 bh1 = *(const float4*)&bhh0[n+4];
        float4 w1  = *(const float4*)&Wih0[n+4];
        float xv = x[(size_t)m*TT + t];
        float4 o0, o1;
        o0.x = tanhf(v0.x + bi0.x + bh0.x + xv*w0.x);
        o0.y = tanhf(v0.y + bi0.y + bh0.y + xv*w0.y);
        o0.z = tanhf(v0.z + bi0.z + bh0.z + xv*w0.z);
        o0.w = tanhf(v0.w + bi0.w + bh0.w + xv*w0.w);
        o1.x = tanhf(v1.x + bi1.x + bh1.x + xv*w1.x);
        o1.y = tanhf(v1.y + bi1.y + bh1.y + xv*w1.y);
        o1.z = tanhf(v1.z + bi1.z + bh1.z + xv*w1.z);
        o1.w = tanhf(v1.w + bi1.w + bh1.w + xv*w1.w);
        *(float4*)&outp[(size_t)m*HH + n]     = o0;
        *(float4*)&outp[(size_t)m*HH + n + 4] = o1;
    } else if (gemm == 1) {
        float4 bi0 = *(const float4*)&bih1[n];
        float4 bh0 = *(const float4*)&bhh1[n];
        float4 bi1 = *(const float4*)&bih1[n+4];
        float4 bh1 = *(const float4*)&bhh1[n+4];
        float4 o0 = make_float4(v0.x+bi0.x+bh0.x, v0.y+bi0.y+bh0.y,
                                v0.z+bi0.z+bh0.z, v0.w+bi0.w+bh0.w);
        float4 o1 = make_float4(v1.x+bi1.x+bh1.x, v1.y+bi1.y+bh1.y,
                                v1.z+bi1.z+bh1.z, v1.w+bi1.w+bh1.w);
        *(float4*)&outp[(size_t)m*HH + n]     = o0;
        *(float4*)&outp[(size_t)m*HH + n + 4] = o1;
    } else {
        const float* pbuf = g_p[(t-2)&1];
        float4 p0 = *(const float4*)&pbuf[(size_t)m*HH + n];
        float4 p1 = *(const float4*)&pbuf[(size_t)m*HH + n + 4];
        float4 o0, o1;
        o0.x = tanhf(v0.x + p0.x); o0.y = tanhf(v0.y + p0.y);
        o0.z = tanhf(v0.z + p0.z); o0.w = tanhf(v0.w + p0.w);
        o1.x = tanhf(v1.x + p1.x); o1.y = tanhf(v1.y + p1.y);
        o1.z = tanhf(v1.z + p1.z); o1.w = tanhf(v1.w + p1.w);
        *(float4*)&outp[(size_t)m*HH + n]     = o0;
        *(float4*)&outp[(size_t)m*HH + n + 4] = o1;
    }
}

// ---------------- FC: out[b,t,v] = h1[t,b,:] @ Wfc[v,:] + bfc[v]  (tf32 mma) ----------------
__global__ void __launch_bounds__(256) fc_kernel(
    const float* __restrict__ Wfc, const float* __restrict__ bfc, float* __restrict__ out)
{
    __shared__ __align__(16) float As[128][36];   // [m][k]
    __shared__ float Bs[32][136];                 // [k][n]

    const float* Ag = g_h1 + (size_t)BB*HH;       // [32768][1024], row m = t*128+b
    int mb = blockIdx.y * 128;
    int nbase = blockIdx.x * 128;
    int tid = threadIdx.x;
    int warp = tid >> 5, lane = tid & 31;
    int wm = warp >> 2, wn = warp & 3;            // 2 x 4 warp grid, warp tile 64x32
    int g = lane >> 2, tig = lane & 3;

    float c[4][4][4];
    #pragma unroll
    for (int i=0;i<4;i++)
        #pragma unroll
        for (int j=0;j<4;j++)
            { c[i][j][0]=0.f; c[i][j][1]=0.f; c[i][j][2]=0.f; c[i][j][3]=0.f; }

    int sm = tid >> 3;
    int skq = tid & 7;

    float4 rA[4], rB[4];

    #pragma unroll
    for (int p=0;p<4;p++){
        rA[p] = *(const float4*)&Ag[(size_t)(mb + sm + p*32)*HH + skq*4];
        rB[p] = *(const float4*)&Wfc[(size_t)(nbase + sm + p*32)*HH + skq*4];
    }
    #pragma unroll
    for (int p=0;p<4;p++){
        float4 a = rA[p];
        *(float4*)&As[sm + p*32][skq*4] =
            make_float4(tf32r(a.x), tf32r(a.y), tf32r(a.z), tf32r(a.w));
        float4 b = rB[p];
        Bs[skq*4+0][sm + p*32] = tf32r(b.x);
        Bs[skq*4+1][sm + p*32] = tf32r(b.y);
        Bs[skq*4+2][sm + p*32] = tf32r(b.z);
        Bs[skq*4+3][sm + p*32] = tf32r(b.w);
    }
    __syncthreads();

    for (int kt = 0; kt < 32; kt++) {
        if (kt < 31) {
            int kb = (kt+1)*32;
            #pragma unroll
            for (int p=0;p<4;p++){
                rA[p] = *(const float4*)&Ag[(size_t)(mb + sm + p*32)*HH + kb + skq*4];
                rB[p] = *(const float4*)&Wfc[(size_t)(nbase + sm + p*32)*HH + kb + skq*4];
            }
        }
        #pragma unroll
        for (int kk=0; kk<4; kk++){
            int ks = kk*8;
            unsigned a[4][4], b[4][2];
            #pragma unroll
            for (int mi=0;mi<4;mi++){
                int mr = wm*64 + mi*16;
                a[mi][0] = __float_as_uint(As[mr+g  ][ks+tig  ]);
                a[mi][1] = __float_as_uint(As[mr+g+8][ks+tig  ]);
                a[mi][2] = __float_as_uint(As[mr+g  ][ks+tig+4]);
                a[mi][3] = __float_as_uint(As[mr+g+8][ks+tig+4]);
            }
            #pragma unroll
            for (int ni=0;ni<4;ni++){
                int nc = wn*32 + ni*8;
                b[ni][0] = __float_as_uint(Bs[ks+tig  ][nc+g]);
                b[ni][1] = __float_as_uint(Bs[ks+tig+4][nc+g]);
            }
            #pragma unroll
            for (int mi=0;mi<4;mi++)
                #pragma unroll
                for (int ni=0;ni<4;ni++){
                    asm volatile(
                        "mma.sync.aligned.m16n8k8.row.col.f32.tf32.tf32.f32 "
                        "{%0,%1,%2,%3}, {%4,%5,%6,%7}, {%8,%9}, {%0,%1,%2,%3};"
                        : "+f"(c[mi][ni][0]), "+f"(c[mi][ni][1]),
                          "+f"(c[mi][ni][2]), "+f"(c[mi][ni][3])
                        : "r"(a[mi][0]), "r"(a[mi][1]), "r"(a[mi][2]), "r"(a[mi][3]),
                          "r"(b[ni][0]), "r"(b[ni][1]));
                }
        }
        __syncthreads();
        if (kt < 31) {
            #pragma unroll
            for (int p=0;p<4;p++){
                float4 a = rA[p];
                *(float4*)&As[sm + p*32][skq*4] =
                    make_float4(tf32r(a.x), tf32r(a.y), tf32r(a.z), tf32r(a.w));
                float4 b = rB[p];
                Bs[skq*4+0][sm + p*32] = tf32r(b.x);
                Bs[skq*4+1][sm + p*32] = tf32r(b.y);
                Bs[skq*4+2][sm + p*32] = tf32r(b.z);
                Bs[skq*4+3][sm + p*32] = tf32r(b.w);
            }
            __syncthreads();
        }
    }

    #pragma unroll
    for (int mi=0;mi<4;mi++){
        #pragma unroll
        for (int ni=0;ni<4;ni++){
            int nc = nbase + wn*32 + ni*8 + tig*2;
            float2 bias = *(const float2*)&bfc[nc];
            int m1 = mb + wm*64 + mi*16 + g;
            int m2 = m1 + 8;
            {
                int bb = m1 & 127, tt = m1 >> 7;
                float2 o = make_float2(c[mi][ni][0] + bias.x, c[mi][ni][1] + bias.y);
                *(float2*)&out[(size_t)bb*TT*VV + (size_t)tt*VV + nc] = o;
            }
            {
                int bb = m2 & 127, tt = m2 >> 7;
                float2 o = make_float2(c[mi][ni][2] + bias.x, c[mi][ni][3] + bias.y);
                *(float2*)&out[(size_t)bb*TT*VV + (size_t)tt*VV + nc] = o;
            }
        }
    }
}

// ---------------- tail: h_n = stack([h0_final, h1_final]) ----------------
__global__ void tail_kernel(float* __restrict__ out){
    int i = blockIdx.x * blockDim.x + threadIdx.x;
    if (i >= 2*BB*HH) return;
    size_t base = (size_t)BB*TT*VV;
    float v = (i < BB*HH) ? g_h0[1][i]
                          : g_h1[(size_t)TT*BB*HH + (i - BB*HH)];
    out[base + i] = v;
}

extern "C" void kernel_launch(void* const* d_in, const int* in_sizes, int n_in,
                              void* d_out, int out_size) {
    const float* x    = (const float*)d_in[0];
    const float* Wih0 = (const float*)d_in[1];
    const float* Whh0 = (const float*)d_in[2];
    const float* bih0 = (const float*)d_in[3];
    const float* bhh0 = (const float*)d_in[4];
    const float* Wih1 = (const float*)d_in[5];
    const float* Whh1 = (const float*)d_in[6];
    const float* bih1 = (const float*)d_in[7];
    const float* bhh1 = (const float*)d_in[8];
    const float* Wfc  = (const float*)d_in[9];
    const float* bfc  = (const float*)d_in[10];
    float* out = (float*)d_out;

    zero_kernel<<<(BB*HH + 255)/256, 256>>>();

    for (int t = 0; t <= TT + 1; t++)
        step_kernel<<<384, 128>>>(t, x, Wih0, Whh0, bih0, bhh0, Wih1, Whh1, bih1, bhh1);

    fc_kernel<<<dim3(32, 256), 256>>>(Wfc, bfc, out);

    long long need = (long long)BB*TT*VV + 2LL*BB*HH;
    if ((long long)out_size >= need)
        tail_kernel<<<(2*BB*HH + 255)/256, 256>>>(out);
}

// round 15
// speedup vs baseline: 2.9002x; 1.4253x over previous
#include <cuda_runtime.h>
#include <cuda_bf16.h>
#include <cstdint>

#define BB 128
#define TT 256
#define HH 1024
#define VV 4096

// ---------------- scratch (device globals; no runtime allocation) ----------------
__device__ __align__(16) float g_h0[2][BB*HH];          // ping-pong h0
__device__ __align__(16) float g_p[2][BB*HH];           // ping-pong p = h0@Wih1^T + b
__device__ __align__(16) float g_zero[BB*HH];           // zeros (h0[-1])
__device__ __align__(16) float g_h1[(TT+1)*(BB*HH)];    // slot(i) = g_h1 + (i+1)*BB*HH; slot(-1)=zeros

__global__ void zero_kernel() {
    int i = blockIdx.x * blockDim.x + threadIdx.x;
    if (i < BB*HH) { g_zero[i] = 0.f; g_h1[i] = 0.f; }
}

__device__ __forceinline__ float tf32r(float v){
    unsigned u; asm("cvt.rna.tf32.f32 %0, %1;" : "=r"(u) : "f"(v));
    return __uint_as_float(u);
}

__device__ __forceinline__ void mma_tf32(float* c, const unsigned* a, const unsigned* b){
    asm volatile(
        "mma.sync.aligned.m16n8k8.row.col.f32.tf32.tf32.f32 "
        "{%0,%1,%2,%3}, {%4,%5,%6,%7}, {%8,%9}, {%0,%1,%2,%3};"
        : "+f"(c[0]), "+f"(c[1]), "+f"(c[2]), "+f"(c[3])
        : "r"(a[0]), "r"(a[1]), "r"(a[2]), "r"(a[3]), "r"(b[0]), "r"(b[1]));
}

// ---------------- recurrent step: 3 independent GEMMs, occupancy-first ----------------
// gemm0: h0[t]   = tanh(x_t*Wih0 + bih0 + bhh0 + h0[t-1]@Whh0^T)      (t in [0,255])
// gemm1: p[t-1]  = h0[t-1]@Wih1^T + bih1 + bhh1                       (t in [1,256])
// gemm2: h1[t-2] = tanh(p[t-2] + h1[t-3]@Whh1^T)                      (t in [2,257])
//
// CTA tile 32(M) x 32(N), 128 threads = 4 warps. Each warp owns a private
// K=256 slice (16 chunks of k16), warp-private RAW-fp32 smem staging ->
// half the L1 traffic of hi/lo staging; 3xTF32 split done IN REGISTERS at
// the consumer. No __syncthreads in the mainloop (only __syncwarp).
// grid = 3 * (4 m-parts * 32 n-parts) = 384 CTAs -> 3 CTAs/SM, one wave.
__global__ void __launch_bounds__(128, 3) step_kernel(
    int t, const float* __restrict__ x,
    const float* __restrict__ Wih0, const float* __restrict__ Whh0,
    const float* __restrict__ bih0, const float* __restrict__ bhh0,
    const float* __restrict__ Wih1, const float* __restrict__ Whh1,
    const float* __restrict__ bih1, const float* __restrict__ bhh1)
{
    // [warp][role 0=A 1=B][row 32][k16 pad 20] raw fp32 = 20 KB
    // pad 20: frag LDS banks (20g+tig)&31 all distinct -> conflict-free;
    // STS.128 bank-groups uniform (4 lanes/group) -> crossbar-optimal.
    __shared__ __align__(16) float SM[4][2][32][20];

    int gemm = blockIdx.x >> 7;
    int r = blockIdx.x & 127;
    int m0 = (r & 3) << 5;      // 0,32,64,96
    int n0 = (r >> 2) << 5;     // 0..992

    const float *A, *W;
    float *outp;
    if (gemm == 0) {
        if (t >= TT) return;
        A = (t == 0) ? g_zero : g_h0[(t-1)&1];
        W = Whh0; outp = g_h0[t&1];
    } else if (gemm == 1) {
        if (t < 1 || t > TT) return;
        A = g_h0[(t-1)&1]; W = Wih1; outp = g_p[(t-1)&1];
    } else {
        if (t < 2) return;
        A = g_h1 + (size_t)(t-2)*(BB*HH);     // slot(t-3)
        W = Whh1;
        outp = g_h1 + (size_t)(t-1)*(BB*HH);  // slot(t-2)
    }

    int tid  = threadIdx.x;
    int warp = tid >> 5, lane = tid & 31;
    int g  = lane >> 2, tig = lane & 3;
    int srow = lane >> 2;          // staging row base 0..7
    int kcol = (lane & 3) * 4;     // staging k column 0,4,8,12

    float (*As)[20] = SM[warp][0];
    float (*Bs)[20] = SM[warp][1];

    float cm[2][4][4];
    #pragma unroll
    for (int i=0;i<2;i++)
        #pragma unroll
        for (int j=0;j<4;j++)
            #pragma unroll
            for (int q=0;q<4;q++) cm[i][j][q]=0.f;

    int kbase = warp << 8;   // K slice [warp*256, warp*256+256)

    float4 rA[4], rB[4];
    // prologue: LDG chunk 0
    #pragma unroll
    for (int i=0;i<4;i++){
        rA[i] = *(const float4*)&A[(size_t)(m0 + srow + 8*i)*HH + kbase + kcol];
        rB[i] = *(const float4*)&W[(size_t)(n0 + srow + 8*i)*HH + kbase + kcol];
    }

    for (int kt = 0; kt < 16; kt++) {
        // stage raw chunk kt (warp-private smem)
        #pragma unroll
        for (int i=0;i<4;i++){
            int row = srow + 8*i;
            *(float4*)&As[row][kcol] = rA[i];
            *(float4*)&Bs[row][kcol] = rB[i];
        }
        // prefetch chunk kt+1 (latency hidden behind compute below)
        if (kt < 15) {
            int kb = kbase + (kt+1)*16;
            #pragma unroll
            for (int i=0;i<4;i++){
                rA[i] = *(const float4*)&A[(size_t)(m0 + srow + 8*i)*HH + kb + kcol];
                rB[i] = *(const float4*)&W[(size_t)(n0 + srow + 8*i)*HH + kb + kcol];
            }
        }
        __syncwarp();
        // compute chunk kt: 2 k8 slices; 3xTF32 split in registers
        #pragma unroll
        for (int kk=0; kk<2; kk++){
            int ks = kk*8;
            float ar[2][4], br[4][2];
            #pragma unroll
            for (int mi=0;mi<2;mi++){
                int mr = mi*16;
                ar[mi][0] = As[mr+g  ][ks+tig  ];
                ar[mi][1] = As[mr+g+8][ks+tig  ];
                ar[mi][2] = As[mr+g  ][ks+tig+4];
                ar[mi][3] = As[mr+g+8][ks+tig+4];
            }
            #pragma unroll
            for (int ni=0;ni<4;ni++){
                int nc = ni*8;
                br[ni][0] = Bs[nc+g][ks+tig  ];
                br[ni][1] = Bs[nc+g][ks+tig+4];
            }
            unsigned ah[2][4], al[2][4], bh[4][2], bl[4][2];
            #pragma unroll
            for (int mi=0;mi<2;mi++)
                #pragma unroll
                for (int j=0;j<4;j++){
                    float h = tf32r(ar[mi][j]);
                    ah[mi][j] = __float_as_uint(h);
                    al[mi][j] = __float_as_uint(tf32r(ar[mi][j] - h));
                }
            #pragma unroll
            for (int ni=0;ni<4;ni++)
                #pragma unroll
                for (int j=0;j<2;j++){
                    float h = tf32r(br[ni][j]);
                    bh[ni][j] = __float_as_uint(h);
                    bl[ni][j] = __float_as_uint(tf32r(br[ni][j] - h));
                }
            #pragma unroll
            for (int mi=0;mi<2;mi++)
                #pragma unroll
                for (int ni=0;ni<4;ni++){
                    mma_tf32(cm[mi][ni], ah[mi], bh[ni]);
                    mma_tf32(cm[mi][ni], al[mi], bh[ni]);
                    mma_tf32(cm[mi][ni], ah[mi], bl[ni]);
                }
        }
        __syncwarp();   // protect staging WAR for next iteration
    }

    // ---------------- cross-warp K reduction ----------------
    // reuse this warp's staging region (1280 floats >= 32*36=1152) as partial tile
    // C-fragment layout: {c0,c1} -> (row g,   cols nc,nc+1)
    //                    {c2,c3} -> (row g+8, cols nc,nc+1)
    float* red = &SM[warp][0][0][0];
    #pragma unroll
    for (int mi=0;mi<2;mi++){
        #pragma unroll
        for (int ni=0;ni<4;ni++){
            int nc = ni*8 + tig*2;
            int r1 = mi*16 + g, r2 = r1 + 8;
            *(float2*)&red[r1*36 + nc] = make_float2(cm[mi][ni][0], cm[mi][ni][1]);
            *(float2*)&red[r2*36 + nc] = make_float2(cm[mi][ni][2], cm[mi][ni][3]);
        }
    }
    __syncthreads();

    // each thread owns one row (rr) and 8 cols (cb..cb+7)
    int rr = tid >> 2, cb = (tid & 3) * 8;
    float4 v0 = make_float4(0,0,0,0), v1 = make_float4(0,0,0,0);
    #pragma unroll
    for (int w=0; w<4; w++){
        const float* rw = &SM[w][0][0][0];
        float4 a = *(const float4*)&rw[rr*36 + cb];
        float4 b = *(const float4*)&rw[rr*36 + cb + 4];
        v0.x += a.x; v0.y += a.y; v0.z += a.z; v0.w += a.w;
        v1.x += b.x; v1.y += b.y; v1.z += b.z; v1.w += b.w;
    }

    int m = m0 + rr, n = n0 + cb;

    if (gemm == 0) {
        float4 bi0 = *(const float4*)&bih0[n];
        float4 bh0 = *(const float4*)&bhh0[n];
        float4 w0  = *(const float4*)&Wih0[n];
        float4 bi1 = *(const float4*)&bih0[n+4];
        float4 bh1 = *(const float4*)&bhh0[n+4];
        float4 w1  = *(const float4*)&Wih0[n+4];
        float xv = x[(size_t)m*TT + t];
        float4 o0, o1;
        o0.x = tanhf(v0.x + bi0.x + bh0.x + xv*w0.x);
        o0.y = tanhf(v0.y + bi0.y + bh0.y + xv*w0.y);
        o0.z = tanhf(v0.z + bi0.z + bh0.z + xv*w0.z);
        o0.w = tanhf(v0.w + bi0.w + bh0.w + xv*w0.w);
        o1.x = tanhf(v1.x + bi1.x + bh1.x + xv*w1.x);
        o1.y = tanhf(v1.y + bi1.y + bh1.y + xv*w1.y);
        o1.z = tanhf(v1.z + bi1.z + bh1.z + xv*w1.z);
        o1.w = tanhf(v1.w + bi1.w + bh1.w + xv*w1.w);
        *(float4*)&outp[(size_t)m*HH + n]     = o0;
        *(float4*)&outp[(size_t)m*HH + n + 4] = o1;
    } else if (gemm == 1) {
        float4 bi0 = *(const float4*)&bih1[n];
        float4 bh0 = *(const float4*)&bhh1[n];
        float4 bi1 = *(const float4*)&bih1[n+4];
        float4 bh1 = *(const float4*)&bhh1[n+4];
        float4 o0 = make_float4(v0.x+bi0.x+bh0.x, v0.y+bi0.y+bh0.y,
                                v0.z+bi0.z+bh0.z, v0.w+bi0.w+bh0.w);
        float4 o1 = make_float4(v1.x+bi1.x+bh1.x, v1.y+bi1.y+bh1.y,
                                v1.z+bi1.z+bh1.z, v1.w+bi1.w+bh1.w);
        *(float4*)&outp[(size_t)m*HH + n]     = o0;
        *(float4*)&outp[(size_t)m*HH + n + 4] = o1;
    } else {
        const float* pbuf = g_p[(t-2)&1];
        float4 p0 = *(const float4*)&pbuf[(size_t)m*HH + n];
        float4 p1 = *(const float4*)&pbuf[(size_t)m*HH + n + 4];
        float4 o0, o1;
        o0.x = tanhf(v0.x + p0.x); o0.y = tanhf(v0.y + p0.y);
        o0.z = tanhf(v0.z + p0.z); o0.w = tanhf(v0.w + p0.w);
        o1.x = tanhf(v1.x + p1.x); o1.y = tanhf(v1.y + p1.y);
        o1.z = tanhf(v1.z + p1.z); o1.w = tanhf(v1.w + p1.w);
        *(float4*)&outp[(size_t)m*HH + n]     = o0;
        *(float4*)&outp[(size_t)m*HH + n + 4] = o1;
    }
}

// ---------------- FC: out[b,t,v] = h1[t,b,:] @ Wfc[v,:] + bfc[v]  (tf32 mma) ----------------
// B staged in [n][k] row layout (conflict-free STS.128, same as As);
// b-frags read directly from [n][k]: bank 4g+tig(+8kk) -> conflict-free.
__global__ void __launch_bounds__(256) fc_kernel(
    const float* __restrict__ Wfc, const float* __restrict__ bfc, float* __restrict__ out)
{
    __shared__ __align__(16) float As[128][36];   // [m][k]
    __shared__ __align__(16) float Bs[128][36];   // [n][k]

    const float* Ag = g_h1 + (size_t)BB*HH;       // [32768][1024], row m = t*128+b
    int mb = blockIdx.y * 128;
    int nbase = blockIdx.x * 128;
    int tid = threadIdx.x;
    int warp = tid >> 5, lane = tid & 31;
    int wm = warp >> 2, wn = warp & 3;            // 2 x 4 warp grid, warp tile 64x32
    int g = lane >> 2, tig = lane & 3;

    float c[4][4][4];
    #pragma unroll
    for (int i=0;i<4;i++)
        #pragma unroll
        for (int j=0;j<4;j++)
            { c[i][j][0]=0.f; c[i][j][1]=0.f; c[i][j][2]=0.f; c[i][j][3]=0.f; }

    int sm = tid >> 3;
    int skq = tid & 7;

    float4 rA[4], rB[4];

    #pragma unroll
    for (int p=0;p<4;p++){
        rA[p] = *(const float4*)&Ag[(size_t)(mb + sm + p*32)*HH + skq*4];
        rB[p] = *(const float4*)&Wfc[(size_t)(nbase + sm + p*32)*HH + skq*4];
    }
    #pragma unroll
    for (int p=0;p<4;p++){
        float4 a = rA[p];
        *(float4*)&As[sm + p*32][skq*4] =
            make_float4(tf32r(a.x), tf32r(a.y), tf32r(a.z), tf32r(a.w));
        float4 b = rB[p];
        *(float4*)&Bs[sm + p*32][skq*4] =
            make_float4(tf32r(b.x), tf32r(b.y), tf32r(b.z), tf32r(b.w));
    }
    __syncthreads();

    for (int kt = 0; kt < 32; kt++) {
        if (kt < 31) {
            int kb = (kt+1)*32;
            #pragma unroll
            for (int p=0;p<4;p++){
                rA[p] = *(const float4*)&Ag[(size_t)(mb + sm + p*32)*HH + kb + skq*4];
                rB[p] = *(const float4*)&Wfc[(size_t)(nbase + sm + p*32)*HH + kb + skq*4];
            }
        }
        #pragma unroll
        for (int kk=0; kk<4; kk++){
            int ks = kk*8;
            unsigned a[4][4], b[4][2];
            #pragma unroll
            for (int mi=0;mi<4;mi++){
                int mr = wm*64 + mi*16;
                a[mi][0] = __float_as_uint(As[mr+g  ][ks+tig  ]);
                a[mi][1] = __float_as_uint(As[mr+g+8][ks+tig  ]);
                a[mi][2] = __float_as_uint(As[mr+g  ][ks+tig+4]);
                a[mi][3] = __float_as_uint(As[mr+g+8][ks+tig+4]);
            }
            #pragma unroll
            for (int ni=0;ni<4;ni++){
                int nc = wn*32 + ni*8;
                b[ni][0] = __float_as_uint(Bs[nc+g][ks+tig  ]);
                b[ni][1] = __float_as_uint(Bs[nc+g][ks+tig+4]);
            }
            #pragma unroll
            for (int mi=0;mi<4;mi++)
                #pragma unroll
                for (int ni=0;ni<4;ni++){
                    asm volatile(
                        "mma.sync.aligned.m16n8k8.row.col.f32.tf32.tf32.f32 "
                        "{%0,%1,%2,%3}, {%4,%5,%6,%7}, {%8,%9}, {%0,%1,%2,%3};"
                        : "+f"(c[mi][ni][0]), "+f"(c[mi][ni][1]),
                          "+f"(c[mi][ni][2]), "+f"(c[mi][ni][3])
                        : "r"(a[mi][0]), "r"(a[mi][1]), "r"(a[mi][2]), "r"(a[mi][3]),
                          "r"(b[ni][0]), "r"(b[ni][1]));
                }
        }
        __syncthreads();
        if (kt < 31) {
            #pragma unroll
            for (int p=0;p<4;p++){
                float4 a = rA[p];
                *(float4*)&As[sm + p*32][skq*4] =
                    make_float4(tf32r(a.x), tf32r(a.y), tf32r(a.z), tf32r(a.w));
                float4 b = rB[p];
                *(float4*)&Bs[sm + p*32][skq*4] =
                    make_float4(tf32r(b.x), tf32r(b.y), tf32r(b.z), tf32r(b.w));
            }
            __syncthreads();
        }
    }

    #pragma unroll
    for (int mi=0;mi<4;mi++){
        #pragma unroll
        for (int ni=0;ni<4;ni++){
            int nc = nbase + wn*32 + ni*8 + tig*2;
            float2 bias = *(const float2*)&bfc[nc];
            int m1 = mb + wm*64 + mi*16 + g;
            int m2 = m1 + 8;
            {
                int bb = m1 & 127, tt = m1 >> 7;
                float2 o = make_float2(c[mi][ni][0] + bias.x, c[mi][ni][1] + bias.y);
                *(float2*)&out[(size_t)bb*TT*VV + (size_t)tt*VV + nc] = o;
            }
            {
                int bb = m2 & 127, tt = m2 >> 7;
                float2 o = make_float2(c[mi][ni][2] + bias.x, c[mi][ni][3] + bias.y);
                *(float2*)&out[(size_t)bb*TT*VV + (size_t)tt*VV + nc] = o;
            }
        }
    }
}

// ---------------- tail: h_n = stack([h0_final, h1_final]) ----------------
__global__ void tail_kernel(float* __restrict__ out){
    int i = blockIdx.x * blockDim.x + threadIdx.x;
    if (i >= 2*BB*HH) return;
    size_t base = (size_t)BB*TT*VV;
    float v = (i < BB*HH) ? g_h0[1][i]
                          : g_h1[(size_t)TT*BB*HH + (i - BB*HH)];
    out[base + i] = v;
}

extern "C" void kernel_launch(void* const* d_in, const int* in_sizes, int n_in,
                              void* d_out, int out_size) {
    const float* x    = (const float*)d_in[0];
    const float* Wih0 = (const float*)d_in[1];
    const float* Whh0 = (const float*)d_in[2];
    const float* bih0 = (const float*)d_in[3];
    const float* bhh0 = (const float*)d_in[4];
    const float* Wih1 = (const float*)d_in[5];
    const float* Whh1 = (const float*)d_in[6];
    const float* bih1 = (const float*)d_in[7];
    const float* bhh1 = (const float*)d_in[8];
    const float* Wfc  = (const float*)d_in[9];
    const float* bfc  = (const float*)d_in[10];
    float* out = (float*)d_out;

    zero_kernel<<<(BB*HH + 255)/256, 256>>>();

    for (int t = 0; t <= TT + 1; t++)
        step_kernel<<<384, 128>>>(t, x, Wih0, Whh0, bih0, bhh0, Wih1, Whh1, bih1, bhh1);

    fc_kernel<<<dim3(32, 256), 256>>>(Wfc, bfc, out);

    long long need = (long long)BB*TT*VV + 2LL*BB*HH;
    if ((long long)out_size >= need)
        tail_kernel<<<(2*BB*HH + 255)/256, 256>>>(out);
}

// round 16
// speedup vs baseline: 3.2192x; 1.1100x over previous
#include <cuda_runtime.h>
#include <cuda_bf16.h>
#include <cstdint>

#define BB 128
#define TT 256
#define HH 1024
#define VV 4096

// ---------------- scratch (device globals; no runtime allocation) ----------------
// Fragment-layout hidden state (A-side, m16n8k8 frag order) and weights (B-side).
__device__ __align__(16) float g_h0f[2][BB*HH];         // ping-pong h0, FRAG layout
__device__ __align__(16) float g_h1f[2][BB*HH];         // ping-pong h1, FRAG layout
__device__ __align__(16) float g_p[2][BB*HH];           // ping-pong p = h0@Wih1^T + b (normal)
__device__ __align__(16) float g_zero[BB*HH];           // zeros (frag of zeros == zeros)
__device__ __align__(16) float g_h1[(TT+1)*(BB*HH)];    // normal layout, slot(i)=g_h1+(i+1)*BB*HH (FC input)
__device__ __align__(16) float g_Wf[3*HH*HH];           // frag-layout Whh0 | Wih1 | Whh1

__global__ void zero_kernel() {
    int i = blockIdx.x * blockDim.x + threadIdx.x;
    if (i < BB*HH) { g_zero[i] = 0.f; g_h1[i] = 0.f; }
}

__device__ __forceinline__ float tf32r(float v){
    unsigned u; asm("cvt.rna.tf32.f32 %0, %1;" : "=r"(u) : "f"(v));
    return __uint_as_float(u);
}

__device__ __forceinline__ void mma_tf32(float* c, const unsigned* a, const unsigned* b){
    asm volatile(
        "mma.sync.aligned.m16n8k8.row.col.f32.tf32.tf32.f32 "
        "{%0,%1,%2,%3}, {%4,%5,%6,%7}, {%8,%9}, {%0,%1,%2,%3};"
        : "+f"(c[0]), "+f"(c[1]), "+f"(c[2]), "+f"(c[3])
        : "r"(a[0]), "r"(a[1]), "r"(a[2]), "r"(a[3]), "r"(b[0]), "r"(b[1]));
}

// ---------------- one-time weight transform: normal [n][k] -> B-frag layout ----------------
// B-frag idx: (((np*4+w)*16+kt)*2+kk)*256 + lane*8 + j
//   n = np*32 + (j>>1)*8 + (lane>>2)
//   k = w*256 + kt*16 + kk*8 + (lane&3) + (j&1)*4
__global__ void wtrans_kernel(const float* __restrict__ W0,
                              const float* __restrict__ W1,
                              const float* __restrict__ W2){
    int i = blockIdx.x * blockDim.x + threadIdx.x;
    if (i >= 3*HH*HH) return;
    int mtx = i >> 20;
    int o = i & (HH*HH - 1);
    int np   = o >> 15;
    int w    = (o >> 13) & 3;
    int kt   = (o >> 9) & 15;
    int kk   = (o >> 8) & 1;
    int lane = (o >> 3) & 31;
    int j    = o & 7;
    int n = np*32 + ((j>>1)<<3) + (lane>>2);
    int k = w*256 + kt*16 + kk*8 + (lane&3) + ((j&1)<<2);
    const float* src = (mtx==0) ? W0 : ((mtx==1) ? W1 : W2);
    g_Wf[i] = src[n*HH + k];
}

// ---------------- recurrent step: 3 GEMMs, zero-smem mainloop ----------------
// gemm0: h0[t]   = tanh(x_t*Wih0 + b + h0[t-1]@Whh0^T)   t in [0,255]
// gemm1: p[t-1]  = h0[t-1]@Wih1^T + b                    t in [1,256]
// gemm2: h1[t-2] = tanh(p[t-2] + h1[t-3]@Whh1^T)         t in [2,257]
//
// CTA 32x32 tile, 4 warps, warp-private K=256 slice. Operands read from
// FRAG-layout gmem with coalesced LDG.128 directly into mma fragments:
// no STS/LDS/syncs in the mainloop. 3xTF32 split in registers.
// A-frag idx: ((((mp*4+w)*16+kt)*2+kk)*2+mi)*128 + lane*4 + j
//   row(in 128) = mp*32 + mi*16 + (lane>>2) + (j&1)*8,  k = w*256+kt*16+kk*8+(lane&3)+(j>>1)*4
__global__ void __launch_bounds__(128, 3) step_kernel(
    int t, const float* __restrict__ x,
    const float* __restrict__ Wih0,
    const float* __restrict__ bih0, const float* __restrict__ bhh0,
    const float* __restrict__ bih1, const float* __restrict__ bhh1)
{
    __shared__ __align__(16) float RED[4][32][36];   // 18KB: cross-warp K reduction

    int gemm = blockIdx.x >> 7;
    int r = blockIdx.x & 127;
    int mp = r & 3;             // m-part: rows [32mp, 32mp+32)
    int np = r >> 2;            // n-strip: cols [32np, 32np+32)
    int m0 = mp << 5, n0 = np << 5;

    const float *A, *Wf;
    float *outp;
    if (gemm == 0) {
        if (t >= TT) return;
        A = (t == 0) ? g_zero : g_h0f[(t-1)&1];
        Wf = g_Wf;                       outp = g_h0f[t&1];
    } else if (gemm == 1) {
        if (t < 1 || t > TT) return;
        A = g_h0f[(t-1)&1];
        Wf = g_Wf + HH*HH;               outp = g_p[(t-1)&1];
    } else {
        if (t < 2) return;
        A = (t < 3) ? g_zero : g_h1f[(t-3)&1];
        Wf = g_Wf + 2*HH*HH;             outp = g_h1f[(t-2)&1];
    }

    int tid  = threadIdx.x;
    int warp = tid >> 5, lane = tid & 31;

    const float* Af = A  + ((mp*4 + warp)*16)*512 + lane*4;
    const float* Bf = Wf + ((np*4 + warp)*16)*512 + lane*8;

    float cm[2][4][4];
    #pragma unroll
    for (int i=0;i<2;i++)
        #pragma unroll
        for (int jq=0;jq<4;jq++)
            #pragma unroll
            for (int q=0;q<4;q++) cm[i][jq][q]=0.f;

    float4 cA[4], cB[4], nA[4], nB[4];

    #define LOADCH(KT, RA, RB) { \
        const float* _ap = Af + (KT)*512; \
        const float* _bp = Bf + (KT)*512; \
        RA[0]=*(const float4*)(_ap);      RA[1]=*(const float4*)(_ap+128); \
        RA[2]=*(const float4*)(_ap+256);  RA[3]=*(const float4*)(_ap+384); \
        RB[0]=*(const float4*)(_bp);      RB[1]=*(const float4*)(_bp+4); \
        RB[2]=*(const float4*)(_bp+256);  RB[3]=*(const float4*)(_bp+260); }

    LOADCH(0, cA, cB)

    #pragma unroll 2
    for (int kt = 0; kt < 16; kt++) {
        if (kt < 15) { LOADCH(kt+1, nA, nB) }
        #pragma unroll
        for (int kk = 0; kk < 2; kk++){
            float4 a0 = cA[kk*2], a1 = cA[kk*2+1];
            float4 b0 = cB[kk*2], b1 = cB[kk*2+1];
            unsigned ah[2][4], al[2][4], bh[4][2], bl[4][2];
            {
                const float* av0 = &a0.x; const float* av1 = &a1.x;
                #pragma unroll
                for (int j=0;j<4;j++){
                    float h0v = tf32r(av0[j]);
                    ah[0][j] = __float_as_uint(h0v);
                    al[0][j] = __float_as_uint(tf32r(av0[j] - h0v));
                    float h1v = tf32r(av1[j]);
                    ah[1][j] = __float_as_uint(h1v);
                    al[1][j] = __float_as_uint(tf32r(av1[j] - h1v));
                }
                const float* bv0 = &b0.x; const float* bv1 = &b1.x;
                #pragma unroll
                for (int j=0;j<4;j++){
                    float hb0 = tf32r(bv0[j]);
                    bh[j>>1][j&1] = __float_as_uint(hb0);
                    bl[j>>1][j&1] = __float_as_uint(tf32r(bv0[j] - hb0));
                    float hb1 = tf32r(bv1[j]);
                    bh[2+(j>>1)][j&1] = __float_as_uint(hb1);
                    bl[2+(j>>1)][j&1] = __float_as_uint(tf32r(bv1[j] - hb1));
                }
            }
            #pragma unroll
            for (int mi=0;mi<2;mi++)
                #pragma unroll
                for (int ni=0;ni<4;ni++){
                    mma_tf32(cm[mi][ni], ah[mi], bh[ni]);
                    mma_tf32(cm[mi][ni], al[mi], bh[ni]);
                    mma_tf32(cm[mi][ni], ah[mi], bl[ni]);
                }
        }
        #pragma unroll
        for (int i=0;i<4;i++){ cA[i]=nA[i]; cB[i]=nB[i]; }
    }
    #undef LOADCH

    // ---------------- cross-warp K reduction ----------------
    // C-fragment: {c0,c1} -> (row g, cols nc,nc+1); {c2,c3} -> (row g+8, ...)
    int g  = lane >> 2, tig = lane & 3;
    #pragma unroll
    for (int mi=0;mi<2;mi++){
        #pragma unroll
        for (int ni=0;ni<4;ni++){
            int nc = ni*8 + tig*2;
            int r1 = mi*16 + g, r2 = r1 + 8;
            *(float2*)&RED[warp][r1][nc] = make_float2(cm[mi][ni][0], cm[mi][ni][1]);
            *(float2*)&RED[warp][r2][nc] = make_float2(cm[mi][ni][2], cm[mi][ni][3]);
        }
    }
    __syncthreads();

    // each thread owns one row (rr) and 8 cols (cb..cb+7)
    int rr = tid >> 2, cb = (tid & 3) * 8;
    float4 v0 = make_float4(0,0,0,0), v1 = make_float4(0,0,0,0);
    #pragma unroll
    for (int w=0; w<4; w++){
        float4 a = *(const float4*)&RED[w][rr][cb];
        float4 b = *(const float4*)&RED[w][rr][cb + 4];
        v0.x += a.x; v0.y += a.y; v0.z += a.z; v0.w += a.w;
        v1.x += b.x; v1.y += b.y; v1.z += b.z; v1.w += b.w;
    }

    int m = m0 + rr, n = n0 + cb;

    // frag-store base for h outputs (gemm0/gemm2): value (m, k=n+q)
    int mi2 = (m>>4)&1, jm = (m>>3)&1, gg = m&7;
    int w2 = n>>8, kt2 = (n>>4)&15, kk2 = (n>>3)&1;
    int fbase = ((((mp*4 + w2)*16 + kt2)*2 + kk2)*2 + mi2)*128 + gg*16 + jm;

    if (gemm == 0) {
        float4 bi0 = *(const float4*)&bih0[n];
        float4 bh0 = *(const float4*)&bhh0[n];
        float4 w0  = *(const float4*)&Wih0[n];
        float4 bi1 = *(const float4*)&bih0[n+4];
        float4 bh1 = *(const float4*)&bhh0[n+4];
        float4 w1  = *(const float4*)&Wih0[n+4];
        float xv = x[(size_t)m*TT + t];
        float o0x = tanhf(v0.x + bi0.x + bh0.x + xv*w0.x);
        float o0y = tanhf(v0.y + bi0.y + bh0.y + xv*w0.y);
        float o0z = tanhf(v0.z + bi0.z + bh0.z + xv*w0.z);
        float o0w = tanhf(v0.w + bi0.w + bh0.w + xv*w0.w);
        float o1x = tanhf(v1.x + bi1.x + bh1.x + xv*w1.x);
        float o1y = tanhf(v1.y + bi1.y + bh1.y + xv*w1.y);
        float o1z = tanhf(v1.z + bi1.z + bh1.z + xv*w1.z);
        float o1w = tanhf(v1.w + bi1.w + bh1.w + xv*w1.w);
        outp[fbase + 0*4 + 0] = o0x;   // tig 0..3, kh=0
        outp[fbase + 1*4 + 0] = o0y;
        outp[fbase + 2*4 + 0] = o0z;
        outp[fbase + 3*4 + 0] = o0w;
        outp[fbase + 0*4 + 2] = o1x;   // kh=1 -> +2
        outp[fbase + 1*4 + 2] = o1y;
        outp[fbase + 2*4 + 2] = o1z;
        outp[fbase + 3*4 + 2] = o1w;
    } else if (gemm == 1) {
        float4 bi0 = *(const float4*)&bih1[n];
        float4 bh0 = *(const float4*)&bhh1[n];
        float4 bi1 = *(const float4*)&bih1[n+4];
        float4 bh1 = *(const float4*)&bhh1[n+4];
        float4 o0 = make_float4(v0.x+bi0.x+bh0.x, v0.y+bi0.y+bh0.y,
                                v0.z+bi0.z+bh0.z, v0.w+bi0.w+bh0.w);
        float4 o1 = make_float4(v1.x+bi1.x+bh1.x, v1.y+bi1.y+bh1.y,
                                v1.z+bi1.z+bh1.z, v1.w+bi1.w+bh1.w);
        *(float4*)&outp[(size_t)m*HH + n]     = o0;
        *(float4*)&outp[(size_t)m*HH + n + 4] = o1;
    } else {
        const float* pbuf = g_p[(t-2)&1];
        float4 p0 = *(const float4*)&pbuf[(size_t)m*HH + n];
        float4 p1 = *(const float4*)&pbuf[(size_t)m*HH + n + 4];
        float o0x = tanhf(v0.x + p0.x), o0y = tanhf(v0.y + p0.y);
        float o0z = tanhf(v0.z + p0.z), o0w = tanhf(v0.w + p0.w);
        float o1x = tanhf(v1.x + p1.x), o1y = tanhf(v1.y + p1.y);
        float o1z = tanhf(v1.z + p1.z), o1w = tanhf(v1.w + p1.w);
        // frag copy (for gemm2-next A)
        outp[fbase + 0*4 + 0] = o0x;
        outp[fbase + 1*4 + 0] = o0y;
        outp[fbase + 2*4 + 0] = o0z;
        outp[fbase + 3*4 + 0] = o0w;
        outp[fbase + 0*4 + 2] = o1x;
        outp[fbase + 1*4 + 2] = o1y;
        outp[fbase + 2*4 + 2] = o1z;
        outp[fbase + 3*4 + 2] = o1w;
        // normal copy (for FC): slot(t-2) = g_h1 + (t-1)*BB*HH
        float* hn = g_h1 + (size_t)(t-1)*(BB*HH);
        *(float4*)&hn[(size_t)m*HH + n]     = make_float4(o0x,o0y,o0z,o0w);
        *(float4*)&hn[(size_t)m*HH + n + 4] = make_float4(o1x,o1y,o1z,o1w);
    }
}

// ---------------- FC: out[b,t,v] = h1[t,b,:] @ Wfc[v,:] + bfc[v]  (tf32 mma) ----------------
__global__ void __launch_bounds__(256) fc_kernel(
    const float* __restrict__ Wfc, const float* __restrict__ bfc, float* __restrict__ out)
{
    __shared__ __align__(16) float As[128][36];   // [m][k]
    __shared__ __align__(16) float Bs[128][36];   // [n][k]

    const float* Ag = g_h1 + (size_t)BB*HH;       // [32768][1024], row m = t*128+b
    int mb = blockIdx.y * 128;
    int nbase = blockIdx.x * 128;
    int tid = threadIdx.x;
    int warp = tid >> 5, lane = tid & 31;
    int wm = warp >> 2, wn = warp & 3;            // 2 x 4 warp grid, warp tile 64x32
    int g = lane >> 2, tig = lane & 3;

    float c[4][4][4];
    #pragma unroll
    for (int i=0;i<4;i++)
        #pragma unroll
        for (int j=0;j<4;j++)
            { c[i][j][0]=0.f; c[i][j][1]=0.f; c[i][j][2]=0.f; c[i][j][3]=0.f; }

    int sm = tid >> 3;
    int skq = tid & 7;

    float4 rA[4], rB[4];

    #pragma unroll
    for (int p=0;p<4;p++){
        rA[p] = *(const float4*)&Ag[(size_t)(mb + sm + p*32)*HH + skq*4];
        rB[p] = *(const float4*)&Wfc[(size_t)(nbase + sm + p*32)*HH + skq*4];
    }
    #pragma unroll
    for (int p=0;p<4;p++){
        float4 a = rA[p];
        *(float4*)&As[sm + p*32][skq*4] =
            make_float4(tf32r(a.x), tf32r(a.y), tf32r(a.z), tf32r(a.w));
        float4 b = rB[p];
        *(float4*)&Bs[sm + p*32][skq*4] =
            make_float4(tf32r(b.x), tf32r(b.y), tf32r(b.z), tf32r(b.w));
    }
    __syncthreads();

    for (int kt = 0; kt < 32; kt++) {
        if (kt < 31) {
            int kb = (kt+1)*32;
            #pragma unroll
            for (int p=0;p<4;p++){
                rA[p] = *(const float4*)&Ag[(size_t)(mb + sm + p*32)*HH + kb + skq*4];
                rB[p] = *(const float4*)&Wfc[(size_t)(nbase + sm + p*32)*HH + kb + skq*4];
            }
        }
        #pragma unroll
        for (int kk=0; kk<4; kk++){
            int ks = kk*8;
            unsigned a[4][4], b[4][2];
            #pragma unroll
            for (int mi=0;mi<4;mi++){
                int mr = wm*64 + mi*16;
                a[mi][0] = __float_as_uint(As[mr+g  ][ks+tig  ]);
                a[mi][1] = __float_as_uint(As[mr+g+8][ks+tig  ]);
                a[mi][2] = __float_as_uint(As[mr+g  ][ks+tig+4]);
                a[mi][3] = __float_as_uint(As[mr+g+8][ks+tig+4]);
            }
            #pragma unroll
            for (int ni=0;ni<4;ni++){
                int nc = wn*32 + ni*8;
                b[ni][0] = __float_as_uint(Bs[nc+g][ks+tig  ]);
                b[ni][1] = __float_as_uint(Bs[nc+g][ks+tig+4]);
            }
            #pragma unroll
            for (int mi=0;mi<4;mi++)
                #pragma unroll
                for (int ni=0;ni<4;ni++){
                    asm volatile(
                        "mma.sync.aligned.m16n8k8.row.col.f32.tf32.tf32.f32 "
                        "{%0,%1,%2,%3}, {%4,%5,%6,%7}, {%8,%9}, {%0,%1,%2,%3};"
                        : "+f"(c[mi][ni][0]), "+f"(c[mi][ni][1]),
                          "+f"(c[mi][ni][2]), "+f"(c[mi][ni][3])
                        : "r"(a[mi][0]), "r"(a[mi][1]), "r"(a[mi][2]), "r"(a[mi][3]),
                          "r"(b[ni][0]), "r"(b[ni][1]));
                }
        }
        __syncthreads();
        if (kt < 31) {
            #pragma unroll
            for (int p=0;p<4;p++){
                float4 a = rA[p];
                *(float4*)&As[sm + p*32][skq*4] =
                    make_float4(tf32r(a.x), tf32r(a.y), tf32r(a.z), tf32r(a.w));
                float4 b = rB[p];
                *(float4*)&Bs[sm + p*32][skq*4] =
                    make_float4(tf32r(b.x), tf32r(b.y), tf32r(b.z), tf32r(b.w));
            }
            __syncthreads();
        }
    }

    #pragma unroll
    for (int mi=0;mi<4;mi++){
        #pragma unroll
        for (int ni=0;ni<4;ni++){
            int nc = nbase + wn*32 + ni*8 + tig*2;
            float2 bias = *(const float2*)&bfc[nc];
            int m1 = mb + wm*64 + mi*16 + g;
            int m2 = m1 + 8;
            {
                int bb = m1 & 127, tt = m1 >> 7;
                float2 o = make_float2(c[mi][ni][0] + bias.x, c[mi][ni][1] + bias.y);
                *(float2*)&out[(size_t)bb*TT*VV + (size_t)tt*VV + nc] = o;
            }
            {
                int bb = m2 & 127, tt = m2 >> 7;
                float2 o = make_float2(c[mi][ni][2] + bias.x, c[mi][ni][3] + bias.y);
                *(float2*)&out[(size_t)bb*TT*VV + (size_t)tt*VV + nc] = o;
            }
        }
    }
}

// ---------------- tail: h_n = stack([h0_final, h1_final]) ----------------
__global__ void tail_kernel(float* __restrict__ out){
    int i = blockIdx.x * blockDim.x + threadIdx.x;
    if (i >= 2*BB*HH) return;
    size_t base = (size_t)BB*TT*VV;
    float v;
    if (i < BB*HH) {
        // h0[255] lives in g_h0f[1] (255&1==1), FRAG layout -> inverse map
        int m = i >> 10, k = i & 1023;
        int mp = m>>5, mi=(m>>4)&1, jm=(m>>3)&1, gg=m&7;
        int w = k>>8, kt=(k>>4)&15, kk=(k>>3)&1, tig=k&3, kh=(k>>2)&1;
        int idx = ((((mp*4+w)*16+kt)*2+kk)*2+mi)*128 + (gg*4+tig)*4 + (kh*2+jm);
        v = g_h0f[1][idx];
    } else {
        v = g_h1[(size_t)TT*(BB*HH) + (i - BB*HH)];   // h1 slot(255), normal layout
    }
    out[base + i] = v;
}

extern "C" void kernel_launch(void* const* d_in, const int* in_sizes, int n_in,
                              void* d_out, int out_size) {
    const float* x    = (const float*)d_in[0];
    const float* Wih0 = (const float*)d_in[1];
    const float* Whh0 = (const float*)d_in[2];
    const float* bih0 = (const float*)d_in[3];
    const float* bhh0 = (const float*)d_in[4];
    const float* Wih1 = (const float*)d_in[5];
    const float* Whh1 = (const float*)d_in[6];
    const float* bih1 = (const float*)d_in[7];
    const float* bhh1 = (const float*)d_in[8];
    const float* Wfc  = (const float*)d_in[9];
    const float* bfc  = (const float*)d_in[10];
    float* out = (float*)d_out;

    zero_kernel<<<(BB*HH + 255)/256, 256>>>();
    wtrans_kernel<<<(3*HH*HH + 255)/256, 256>>>(Whh0, Wih1, Whh1);

    for (int t = 0; t <= TT + 1; t++)
        step_kernel<<<384, 128>>>(t, x, Wih0, bih0, bhh0, bih1, bhh1);

    fc_kernel<<<dim3(32, 256), 256>>>(Wfc, bfc, out);

    long long need = (long long)BB*TT*VV + 2LL*BB*HH;
    if ((long long)out_size >= need)
        tail_kernel<<<(2*BB*HH + 255)/256, 256>>>(out);
}

// round 17
// speedup vs baseline: 3.4698x; 1.0779x over previous
#include <cuda_runtime.h>
#include <cuda_bf16.h>
#include <cstdint>

#define BB 128
#define TT 256
#define HH 1024
#define VV 4096

// ---------------- scratch (device globals; no runtime allocation) ----------------
// Fragment-layout hidden state (A-side, m16n8k8 frag order) and PRE-SPLIT weights (B-side).
__device__ __align__(16) float g_h0f[2][BB*HH];         // ping-pong h0, FRAG layout
__device__ __align__(16) float g_h1f[2][BB*HH];         // ping-pong h1, FRAG layout
__device__ __align__(16) float g_p[2][BB*HH];           // ping-pong p = h0@Wih1^T + b (normal)
__device__ __align__(16) float g_zero[BB*HH];           // zeros (frag of zeros == zeros)
__device__ __align__(16) float g_h1[(TT+1)*(BB*HH)];    // normal layout, slot(i)=g_h1+(i+1)*BB*HH (FC input)
// [mtx][hi|lo][HH*HH] frag-layout: Whh0 | Wih1 | Whh1, each split hi/lo once.
__device__ __align__(16) float g_Wf[3*2*HH*HH];

__global__ void zero_kernel() {
    int i = blockIdx.x * blockDim.x + threadIdx.x;
    if (i < BB*HH) { g_zero[i] = 0.f; g_h1[i] = 0.f; }
}

__device__ __forceinline__ float tf32r(float v){
    unsigned u; asm("cvt.rna.tf32.f32 %0, %1;" : "=r"(u) : "f"(v));
    return __uint_as_float(u);
}

__device__ __forceinline__ void mma_tf32(float* c, const unsigned* a, const unsigned* b){
    asm volatile(
        "mma.sync.aligned.m16n8k8.row.col.f32.tf32.tf32.f32 "
        "{%0,%1,%2,%3}, {%4,%5,%6,%7}, {%8,%9}, {%0,%1,%2,%3};"
        : "+f"(c[0]), "+f"(c[1]), "+f"(c[2]), "+f"(c[3])
        : "r"(a[0]), "r"(a[1]), "r"(a[2]), "r"(a[3]), "r"(b[0]), "r"(b[1]));
}

// ---------------- one-time weight transform: normal [n][k] -> PRE-SPLIT B-frag layout ----------
// B-frag idx: (((np*4+w)*16+kt)*2+kk)*256 + lane*8 + j
//   n = np*32 + (j>>1)*8 + (lane>>2)
//   k = w*256 + kt*16 + kk*8 + (lane&3) + (j&1)*4
// hi at [mtx][0], lo at [mtx][1].
__global__ void wtrans_kernel(const float* __restrict__ W0,
                              const float* __restrict__ W1,
                              const float* __restrict__ W2){
    int i = blockIdx.x * blockDim.x + threadIdx.x;
    if (i >= 3*HH*HH) return;
    int mtx = i >> 20;
    int o = i & (HH*HH - 1);
    int np   = o >> 15;
    int w    = (o >> 13) & 3;
    int kt   = (o >> 9) & 15;
    int kk   = (o >> 8) & 1;
    int lane = (o >> 3) & 31;
    int j    = o & 7;
    int n = np*32 + ((j>>1)<<3) + (lane>>2);
    int k = w*256 + kt*16 + kk*8 + (lane&3) + ((j&1)<<2);
    const float* src = (mtx==0) ? W0 : ((mtx==1) ? W1 : W2);
    float v = src[n*HH + k];
    float h = tf32r(v);
    g_Wf[(size_t)mtx*2*HH*HH + o]         = h;
    g_Wf[(size_t)mtx*2*HH*HH + HH*HH + o] = tf32r(v - h);
}

// ---------------- recurrent step: 3 GEMMs, zero-smem zero-B-cvt mainloop ----------------
// gemm0: h0[t]   = tanh(x_t*Wih0 + b + h0[t-1]@Whh0^T)   t in [0,255]
// gemm1: p[t-1]  = h0[t-1]@Wih1^T + b                    t in [1,256]
// gemm2: h1[t-2] = tanh(p[t-2] + h1[t-3]@Whh1^T)         t in [2,257]
//
// CTA 32x32 tile, 4 warps, warp-private K=256 slice. A (h state) loaded from
// frag-layout gmem + in-register 3xTF32 split; B (weights) loaded PRE-SPLIT
// hi/lo (zero ALU). No STS/LDS/syncs in the mainloop.
__global__ void __launch_bounds__(128, 3) step_kernel(
    int t, const float* __restrict__ x,
    const float* __restrict__ Wih0,
    const float* __restrict__ bih0, const float* __restrict__ bhh0,
    const float* __restrict__ bih1, const float* __restrict__ bhh1)
{
    __shared__ __align__(16) float RED[4][32][36];   // 18KB: cross-warp K reduction

    int gemm = blockIdx.x >> 7;
    int r = blockIdx.x & 127;
    int mp = r & 3;             // m-part: rows [32mp, 32mp+32)
    int np = r >> 2;            // n-strip: cols [32np, 32np+32)
    int m0 = mp << 5, n0 = np << 5;

    const float *A, *Wb;
    float *outp;
    if (gemm == 0) {
        if (t >= TT) return;
        A = (t == 0) ? g_zero : g_h0f[(t-1)&1];
        Wb = g_Wf;                       outp = g_h0f[t&1];
    } else if (gemm == 1) {
        if (t < 1 || t > TT) return;
        A = g_h0f[(t-1)&1];
        Wb = g_Wf + 2*HH*HH;             outp = g_p[(t-1)&1];
    } else {
        if (t < 2) return;
        A = (t < 3) ? g_zero : g_h1f[(t-3)&1];
        Wb = g_Wf + 4*HH*HH;             outp = g_h1f[(t-2)&1];
    }

    int tid  = threadIdx.x;
    int warp = tid >> 5, lane = tid & 31;

    const float* Af  = A  + ((mp*4 + warp)*16)*512 + lane*4;
    const float* Bfh = Wb + ((np*4 + warp)*16)*512 + lane*8;
    const float* Bfl = Bfh + HH*HH;

    float cm[2][4][4];
    #pragma unroll
    for (int i=0;i<2;i++)
        #pragma unroll
        for (int jq=0;jq<4;jq++)
            #pragma unroll
            for (int q=0;q<4;q++) cm[i][jq][q]=0.f;

    float4 cA[4], cBH[4], cBL[4], nA[4], nBH[4], nBL[4];

    #define LOADCH(KT, RA, RBH, RBL) { \
        const float* _ap = Af  + (KT)*512; \
        const float* _bh = Bfh + (KT)*512; \
        const float* _bl = Bfl + (KT)*512; \
        RA[0]=*(const float4*)(_ap);      RA[1]=*(const float4*)(_ap+128); \
        RA[2]=*(const float4*)(_ap+256);  RA[3]=*(const float4*)(_ap+384); \
        RBH[0]=*(const float4*)(_bh);     RBH[1]=*(const float4*)(_bh+4); \
        RBH[2]=*(const float4*)(_bh+256); RBH[3]=*(const float4*)(_bh+260); \
        RBL[0]=*(const float4*)(_bl);     RBL[1]=*(const float4*)(_bl+4); \
        RBL[2]=*(const float4*)(_bl+256); RBL[3]=*(const float4*)(_bl+260); }

    LOADCH(0, cA, cBH, cBL)

    #pragma unroll 2
    for (int kt = 0; kt < 16; kt++) {
        if (kt < 15) { LOADCH(kt+1, nA, nBH, nBL) }
        #pragma unroll
        for (int kk = 0; kk < 2; kk++){
            float4 a0 = cA[kk*2], a1 = cA[kk*2+1];
            unsigned ah[2][4], al[2][4], bh[4][2], bl[4][2];
            {
                const float* av0 = &a0.x; const float* av1 = &a1.x;
                #pragma unroll
                for (int j=0;j<4;j++){
                    float h0v = tf32r(av0[j]);
                    ah[0][j] = __float_as_uint(h0v);
                    al[0][j] = __float_as_uint(tf32r(av0[j] - h0v));
                    float h1v = tf32r(av1[j]);
                    ah[1][j] = __float_as_uint(h1v);
                    al[1][j] = __float_as_uint(tf32r(av1[j] - h1v));
                }
                // B pre-split: pure bit-reinterpret, zero ALU
                const float* bh0 = &cBH[kk*2].x; const float* bh1 = &cBH[kk*2+1].x;
                const float* bl0 = &cBL[kk*2].x; const float* bl1 = &cBL[kk*2+1].x;
                #pragma unroll
                for (int j=0;j<4;j++){
                    bh[j>>1][j&1]     = __float_as_uint(bh0[j]);
                    bh[2+(j>>1)][j&1] = __float_as_uint(bh1[j]);
                    bl[j>>1][j&1]     = __float_as_uint(bl0[j]);
                    bl[2+(j>>1)][j&1] = __float_as_uint(bl1[j]);
                }
            }
            #pragma unroll
            for (int mi=0;mi<2;mi++)
                #pragma unroll
                for (int ni=0;ni<4;ni++){
                    mma_tf32(cm[mi][ni], ah[mi], bh[ni]);
                    mma_tf32(cm[mi][ni], al[mi], bh[ni]);
                    mma_tf32(cm[mi][ni], ah[mi], bl[ni]);
                }
        }
        #pragma unroll
        for (int i=0;i<4;i++){ cA[i]=nA[i]; cBH[i]=nBH[i]; cBL[i]=nBL[i]; }
    }
    #undef LOADCH

    // ---------------- cross-warp K reduction ----------------
    // C-fragment: {c0,c1} -> (row g, cols nc,nc+1); {c2,c3} -> (row g+8, ...)
    int g  = lane >> 2, tig = lane & 3;
    #pragma unroll
    for (int mi=0;mi<2;mi++){
        #pragma unroll
        for (int ni=0;ni<4;ni++){
            int nc = ni*8 + tig*2;
            int r1 = mi*16 + g, r2 = r1 + 8;
            *(float2*)&RED[warp][r1][nc] = make_float2(cm[mi][ni][0], cm[mi][ni][1]);
            *(float2*)&RED[warp][r2][nc] = make_float2(cm[mi][ni][2], cm[mi][ni][3]);
        }
    }
    __syncthreads();

    // each thread owns one row (rr) and 8 cols (cb..cb+7)
    int rr = tid >> 2, cb = (tid & 3) * 8;
    float4 v0 = make_float4(0,0,0,0), v1 = make_float4(0,0,0,0);
    #pragma unroll
    for (int w=0; w<4; w++){
        float4 a = *(const float4*)&RED[w][rr][cb];
        float4 b = *(const float4*)&RED[w][rr][cb + 4];
        v0.x += a.x; v0.y += a.y; v0.z += a.z; v0.w += a.w;
        v1.x += b.x; v1.y += b.y; v1.z += b.z; v1.w += b.w;
    }

    int m = m0 + rr, n = n0 + cb;

    // frag-store base for h outputs (gemm0/gemm2): value (m, k=n+q)
    int mi2 = (m>>4)&1, jm = (m>>3)&1, gg = m&7;
    int w2 = n>>8, kt2 = (n>>4)&15, kk2 = (n>>3)&1;
    int fbase = ((((mp*4 + w2)*16 + kt2)*2 + kk2)*2 + mi2)*128 + gg*16 + jm;

    if (gemm == 0) {
        float4 bi0 = *(const float4*)&bih0[n];
        float4 bh0 = *(const float4*)&bhh0[n];
        float4 w0  = *(const float4*)&Wih0[n];
        float4 bi1 = *(const float4*)&bih0[n+4];
        float4 bh1 = *(const float4*)&bhh0[n+4];
        float4 w1  = *(const float4*)&Wih0[n+4];
        float xv = x[(size_t)m*TT + t];
        float o0x = tanhf(v0.x + bi0.x + bh0.x + xv*w0.x);
        float o0y = tanhf(v0.y + bi0.y + bh0.y + xv*w0.y);
        float o0z = tanhf(v0.z + bi0.z + bh0.z + xv*w0.z);
        float o0w = tanhf(v0.w + bi0.w + bh0.w + xv*w0.w);
        float o1x = tanhf(v1.x + bi1.x + bh1.x + xv*w1.x);
        float o1y = tanhf(v1.y + bi1.y + bh1.y + xv*w1.y);
        float o1z = tanhf(v1.z + bi1.z + bh1.z + xv*w1.z);
        float o1w = tanhf(v1.w + bi1.w + bh1.w + xv*w1.w);
        outp[fbase + 0*4 + 0] = o0x;   // tig 0..3, kh=0
        outp[fbase + 1*4 + 0] = o0y;
        outp[fbase + 2*4 + 0] = o0z;
        outp[fbase + 3*4 + 0] = o0w;
        outp[fbase + 0*4 + 2] = o1x;   // kh=1 -> +2
        outp[fbase + 1*4 + 2] = o1y;
        outp[fbase + 2*4 + 2] = o1z;
        outp[fbase + 3*4 + 2] = o1w;
    } else if (gemm == 1) {
        float4 bi0 = *(const float4*)&bih1[n];
        float4 bh0 = *(const float4*)&bhh1[n];
        float4 bi1 = *(const float4*)&bih1[n+4];
        float4 bh1 = *(const float4*)&bhh1[n+4];
        float4 o0 = make_float4(v0.x+bi0.x+bh0.x, v0.y+bi0.y+bh0.y,
                                v0.z+bi0.z+bh0.z, v0.w+bi0.w+bh0.w);
        float4 o1 = make_float4(v1.x+bi1.x+bh1.x, v1.y+bi1.y+bh1.y,
                                v1.z+bi1.z+bh1.z, v1.w+bi1.w+bh1.w);
        *(float4*)&outp[(size_t)m*HH + n]     = o0;
        *(float4*)&outp[(size_t)m*HH + n + 4] = o1;
    } else {
        const float* pbuf = g_p[(t-2)&1];
        float4 p0 = *(const float4*)&pbuf[(size_t)m*HH + n];
        float4 p1 = *(const float4*)&pbuf[(size_t)m*HH + n + 4];
        float o0x = tanhf(v0.x + p0.x), o0y = tanhf(v0.y + p0.y);
        float o0z = tanhf(v0.z + p0.z), o0w = tanhf(v0.w + p0.w);
        float o1x = tanhf(v1.x + p1.x), o1y = tanhf(v1.y + p1.y);
        float o1z = tanhf(v1.z + p1.z), o1w = tanhf(v1.w + p1.w);
        // frag copy (for gemm2-next A)
        outp[fbase + 0*4 + 0] = o0x;
        outp[fbase + 1*4 + 0] = o0y;
        outp[fbase + 2*4 + 0] = o0z;
        outp[fbase + 3*4 + 0] = o0w;
        outp[fbase + 0*4 + 2] = o1x;
        outp[fbase + 1*4 + 2] = o1y;
        outp[fbase + 2*4 + 2] = o1z;
        outp[fbase + 3*4 + 2] = o1w;
        // normal copy (for FC): slot(t-2) = g_h1 + (t-1)*BB*HH
        float* hn = g_h1 + (size_t)(t-1)*(BB*HH);
        *(float4*)&hn[(size_t)m*HH + n]     = make_float4(o0x,o0y,o0z,o0w);
        *(float4*)&hn[(size_t)m*HH + n + 4] = make_float4(o1x,o1y,o1z,o1w);
    }
}

// ---------------- FC: out[b,t,v] = h1[t,b,:] @ Wfc[v,:] + bfc[v]  (tf32 mma) ----------------
__global__ void __launch_bounds__(256) fc_kernel(
    const float* __restrict__ Wfc, const float* __restrict__ bfc, float* __restrict__ out)
{
    __shared__ __align__(16) float As[128][36];   // [m][k]
    __shared__ __align__(16) float Bs[128][36];   // [n][k]

    const float* Ag = g_h1 + (size_t)BB*HH;       // [32768][1024], row m = t*128+b
    int mb = blockIdx.y * 128;
    int nbase = blockIdx.x * 128;
    int tid = threadIdx.x;
    int warp = tid >> 5, lane = tid & 31;
    int wm = warp >> 2, wn = warp & 3;            // 2 x 4 warp grid, warp tile 64x32
    int g = lane >> 2, tig = lane & 3;

    float c[4][4][4];
    #pragma unroll
    for (int i=0;i<4;i++)
        #pragma unroll
        for (int j=0;j<4;j++)
            { c[i][j][0]=0.f; c[i][j][1]=0.f; c[i][j][2]=0.f; c[i][j][3]=0.f; }

    int sm = tid >> 3;
    int skq = tid & 7;

    float4 rA[4], rB[4];

    #pragma unroll
    for (int p=0;p<4;p++){
        rA[p] = *(const float4*)&Ag[(size_t)(mb + sm + p*32)*HH + skq*4];
        rB[p] = *(const float4*)&Wfc[(size_t)(nbase + sm + p*32)*HH + skq*4];
    }
    #pragma unroll
    for (int p=0;p<4;p++){
        float4 a = rA[p];
        *(float4*)&As[sm + p*32][skq*4] =
            make_float4(tf32r(a.x), tf32r(a.y), tf32r(a.z), tf32r(a.w));
        float4 b = rB[p];
        *(float4*)&Bs[sm + p*32][skq*4] =
            make_float4(tf32r(b.x), tf32r(b.y), tf32r(b.z), tf32r(b.w));
    }
    __syncthreads();

    for (int kt = 0; kt < 32; kt++) {
        if (kt < 31) {
            int kb = (kt+1)*32;
            #pragma unroll
            for (int p=0;p<4;p++){
                rA[p] = *(const float4*)&Ag[(size_t)(mb + sm + p*32)*HH + kb + skq*4];
                rB[p] = *(const float4*)&Wfc[(size_t)(nbase + sm + p*32)*HH + kb + skq*4];
            }
        }
        #pragma unroll
        for (int kk=0; kk<4; kk++){
            int ks = kk*8;
            unsigned a[4][4], b[4][2];
            #pragma unroll
            for (int mi=0;mi<4;mi++){
                int mr = wm*64 + mi*16;
                a[mi][0] = __float_as_uint(As[mr+g  ][ks+tig  ]);
                a[mi][1] = __float_as_uint(As[mr+g+8][ks+tig  ]);
                a[mi][2] = __float_as_uint(As[mr+g  ][ks+tig+4]);
                a[mi][3] = __float_as_uint(As[mr+g+8][ks+tig+4]);
            }
            #pragma unroll
            for (int ni=0;ni<4;ni++){
                int nc = wn*32 + ni*8;
                b[ni][0] = __float_as_uint(Bs[nc+g][ks+tig  ]);
                b[ni][1] = __float_as_uint(Bs[nc+g][ks+tig+4]);
            }
            #pragma unroll
            for (int mi=0;mi<4;mi++)
                #pragma unroll
                for (int ni=0;ni<4;ni++){
                    asm volatile(
                        "mma.sync.aligned.m16n8k8.row.col.f32.tf32.tf32.f32 "
                        "{%0,%1,%2,%3}, {%4,%5,%6,%7}, {%8,%9}, {%0,%1,%2,%3};"
                        : "+f"(c[mi][ni][0]), "+f"(c[mi][ni][1]),
                          "+f"(c[mi][ni][2]), "+f"(c[mi][ni][3])
                        : "r"(a[mi][0]), "r"(a[mi][1]), "r"(a[mi][2]), "r"(a[mi][3]),
                          "r"(b[ni][0]), "r"(b[ni][1]));
                }
        }
        __syncthreads();
        if (kt < 31) {
            #pragma unroll
            for (int p=0;p<4;p++){
                float4 a = rA[p];
                *(float4*)&As[sm + p*32][skq*4] =
                    make_float4(tf32r(a.x), tf32r(a.y), tf32r(a.z), tf32r(a.w));
                float4 b = rB[p];
                *(float4*)&Bs[sm + p*32][skq*4] =
                    make_float4(tf32r(b.x), tf32r(b.y), tf32r(b.z), tf32r(b.w));
            }
            __syncthreads();
        }
    }

    #pragma unroll
    for (int mi=0;mi<4;mi++){
        #pragma unroll
        for (int ni=0;ni<4;ni++){
            int nc = nbase + wn*32 + ni*8 + tig*2;
            float2 bias = *(const float2*)&bfc[nc];
            int m1 = mb + wm*64 + mi*16 + g;
            int m2 = m1 + 8;
            {
                int bb = m1 & 127, tt = m1 >> 7;
                float2 o = make_float2(c[mi][ni][0] + bias.x, c[mi][ni][1] + bias.y);
                *(float2*)&out[(size_t)bb*TT*VV + (size_t)tt*VV + nc] = o;
            }
            {
                int bb = m2 & 127, tt = m2 >> 7;
                float2 o = make_float2(c[mi][ni][2] + bias.x, c[mi][ni][3] + bias.y);
                *(float2*)&out[(size_t)bb*TT*VV + (size_t)tt*VV + nc] = o;
            }
        }
    }
}

// ---------------- tail: h_n = stack([h0_final, h1_final]) ----------------
__global__ void tail_kernel(float* __restrict__ out){
    int i = blockIdx.x * blockDim.x + threadIdx.x;
    if (i >= 2*BB*HH) return;
    size_t base = (size_t)BB*TT*VV;
    float v;
    if (i < BB*HH) {
        // h0[255] lives in g_h0f[1] (255&1==1), FRAG layout -> inverse map
        int m = i >> 10, k = i & 1023;
        int mp = m>>5, mi=(m>>4)&1, jm=(m>>3)&1, gg=m&7;
        int w = k>>8, kt=(k>>4)&15, kk=(k>>3)&1, tig=k&3, kh=(k>>2)&1;
        int idx = ((((mp*4+w)*16+kt)*2+kk)*2+mi)*128 + (gg*4+tig)*4 + (kh*2+jm);
        v = g_h0f[1][idx];
    } else {
        v = g_h1[(size_t)TT*(BB*HH) + (i - BB*HH)];   // h1 slot(255), normal layout
    }
    out[base + i] = v;
}

extern "C" void kernel_launch(void* const* d_in, const int* in_sizes, int n_in,
                              void* d_out, int out_size) {
    const float* x    = (const float*)d_in[0];
    const float* Wih0 = (const float*)d_in[1];
    const float* Whh0 = (const float*)d_in[2];
    const float* bih0 = (const float*)d_in[3];
    const float* bhh0 = (const float*)d_in[4];
    const float* Wih1 = (const float*)d_in[5];
    const float* Whh1 = (const float*)d_in[6];
    const float* bih1 = (const float*)d_in[7];
    const float* bhh1 = (const float*)d_in[8];
    const float* Wfc  = (const float*)d_in[9];
    const float* bfc  = (const float*)d_in[10];
    float* out = (float*)d_out;

    zero_kernel<<<(BB*HH + 255)/256, 256>>>();
    wtrans_kernel<<<(3*HH*HH + 255)/256, 256>>>(Whh0, Wih1, Whh1);

    for (int t = 0; t <= TT + 1; t++)
        step_kernel<<<384, 128>>>(t, x, Wih0, bih0, bhh0, bih1, bhh1);

    fc_kernel<<<dim3(32, 256), 256>>>(Wfc, bfc, out);

    long long need = (long long)BB*TT*VV + 2LL*BB*HH;
    if ((long long)out_size >= need)
        tail_kernel<<<(2*BB*HH + 255)/256, 256>>>(out);
}